// round 12
// baseline (speedup 1.0000x reference)
#include <cuda_runtime.h>
#include <cstdint>

#define NMAX 100000
#define EMAX 1600000
#define NLYR 3

// Device scratch.
__device__ __align__(16) float g_all[(size_t)NMAX * 512];
__device__ __align__(16) float g_egoA[(size_t)NMAX * 128];  // ego ping
__device__ __align__(16) float g_egoB[(size_t)NMAX * 128];  // ego pong
// Pre-split bf16 weights: [l][chunk 0..7][hi/lo][od 0..127][k 0..31]
__device__ __align__(16) unsigned short g_wbf[NLYR * 8 * 2 * 128 * 32];
// CSR built once per launch.
__device__ int   g_rowptr[NMAX];
__device__ int   g_cnt[NMAX];
__device__ int   g_off[NMAX];
__device__ int   g_total;
__device__ int   g_ecol[EMAX];
__device__ float g_ewc[EMAX];

// ---------------------------------------------------------------------------
__device__ __forceinline__ uint32_t smem_to_u32(const void* p) {
    uint32_t a;
    asm("{ .reg .u64 t; cvta.to.shared.u64 t, %1; cvt.u32.u64 %0, t; }"
        : "=r"(a) : "l"(p));
    return a;
}
// pack two floats to bf16x2 (a -> upper, b -> lower)
__device__ __forceinline__ uint32_t bf16x2_of(float a, float b) {
    uint32_t r;
    asm("cvt.rn.bf16x2.f32 %0, %1, %2;" : "=r"(r) : "f"(a), "f"(b));
    return r;
}
__device__ __forceinline__ void ldmx4(uint32_t* r, uint32_t addr) {
    asm volatile("ldmatrix.sync.aligned.m8n8.x4.shared.b16 {%0,%1,%2,%3}, [%4];"
                 : "=r"(r[0]), "=r"(r[1]), "=r"(r[2]), "=r"(r[3]) : "r"(addr));
}
__device__ __forceinline__ void mma_bf16(float* c, const uint32_t* a,
                                         const uint32_t* b) {
    asm volatile(
        "mma.sync.aligned.m16n8k16.row.col.f32.bf16.bf16.f32 "
        "{%0,%1,%2,%3}, {%4,%5,%6,%7}, {%8,%9}, {%0,%1,%2,%3};"
        : "+f"(c[0]), "+f"(c[1]), "+f"(c[2]), "+f"(c[3])
        : "r"(a[0]), "r"(a[1]), "r"(a[2]), "r"(a[3]), "r"(b[0]), "r"(b[1]));
}

// ---------------------------------------------------------------------------
// pack_weights: stacked [gc_w | bi_w] K=256, split to bf16 hi+lo.
// ---------------------------------------------------------------------------
__global__ void pack_weights(const float* __restrict__ gw,
                             const float* __restrict__ bw) {
    int idx = blockIdx.x * blockDim.x + threadIdx.x;
    if (idx >= NLYR * 128 * 256) return;
    int l  = idx >> 15;
    int r  = idx & 32767;
    int od = r >> 8;
    int k  = r & 255;
    float x = (k < 128) ? gw[l * 16384 + od * 128 + k]
                        : bw[l * 16384 + od * 128 + (k - 128)];
    uint32_t h2 = bf16x2_of(x, x);
    float xh = __uint_as_float(h2 & 0xffff0000u);
    uint32_t l2 = bf16x2_of(x - xh, x - xh);
    int c = k >> 5, q = k & 31;
    size_t base = ((size_t)((l * 8 + c) * 2) * 128 + od) * 32 + q;
    g_wbf[base]            = (unsigned short)(h2 >> 16);
    g_wbf[base + 128 * 32] = (unsigned short)(l2 >> 16);
}

// ---------------------------------------------------------------------------
__global__ void init_copy(const float4* __restrict__ emb4, int n) {
    int i = blockIdx.x * blockDim.x + threadIdx.x;
    if (i >= n * 32) return;
    int node = i >> 5, d4 = i & 31;
    float4 v = emb4[i];
    ((float4*)g_all)[(size_t)node * 128 + d4] = v;
    ((float4*)g_egoA)[i] = v;
    if (d4 == 0) { g_cnt[node] = 0; g_off[node] = 0; }
    if (i == 0) g_total = 0;
}

// ---------------------------------------------------------------------------
// CSR build (proven path).
// ---------------------------------------------------------------------------
__global__ void csr_hist(const int* __restrict__ ei, int E) {
    int e = blockIdx.x * blockDim.x + threadIdx.x;
    if (e < E) atomicAdd(&g_cnt[ei[e]], 1);
}

__global__ __launch_bounds__(256) void csr_offsets(int n) {
    __shared__ int wbase[8];
    int tid  = threadIdx.x;
    int lane = tid & 31;
    int w    = tid >> 5;
    int i    = blockIdx.x * 256 + tid;
    int cnt  = (i < n) ? g_cnt[i] : 0;

    int pre = cnt;
#pragma unroll
    for (int off = 1; off < 32; off <<= 1) {
        int v = __shfl_up_sync(0xffffffffu, pre, off);
        if (lane >= off) pre += v;
    }
    if (lane == 31) wbase[w] = pre;
    __syncthreads();
    if (w == 0) {
        int orig = (lane < 8) ? wbase[lane] : 0;
        int s = orig;
#pragma unroll
        for (int off = 1; off < 8; off <<= 1) {
            int v = __shfl_up_sync(0xffffffffu, s, off);
            if (lane >= off) s += v;
        }
        int total = __shfl_sync(0xffffffffu, s, 7);
        int base = 0;
        if (lane == 7) base = atomicAdd(&g_total, total);
        base = __shfl_sync(0xffffffffu, base, 7);
        if (lane < 8) wbase[lane] = base + s - orig;
    }
    __syncthreads();
    if (i < n) g_rowptr[i] = wbase[w] + pre - cnt;
}

__global__ void csr_scatter(const int* __restrict__ ei,
                            const float* __restrict__ ew, int E) {
    int e = blockIdx.x * blockDim.x + threadIdx.x;
    if (e >= E) return;
    int row = ei[e];
    int col = ei[E + e];
    int pos = g_rowptr[row] + atomicAdd(&g_off[row], 1);
    g_ecol[pos] = col;
    g_ewc[pos]  = ew[e];
}

// ---------------------------------------------------------------------------
// Fused layer: in-block CSR SpMM (msg -> smem) + split-bf16 warp MMA.
//   C[64 nodes][128 od] = A[64][256] * W[128][256]^T,  A = [msg | ego*msg]
//   3 terms: Ah*Wh + Ah*Wl + Al*Wh, fp32 register accumulate.
// Block 256 thr / 8 warps; warp (wm=w>>2, wn=w&3) owns m32 x n32.
// Dynamic smem (63488 B):
//   [0:32768)      msgS fp32 [64][128]    (alive through chunk 7 A-fill)
//   [32768:63488)  bf16 tiles A hi/lo (5120 ea) + W hi/lo (10240 ea), PITCH 40
//   epilogue overlays Vs[64][132] fp32 at offset 0.
// ---------------------------------------------------------------------------
#define PITCH 40                   // shorts per row (80 B), ldmatrix-safe
#define TL     32768               // tiles base
#define TA_H  (TL + 0)
#define TA_L  (TL + 5120)
#define TW_H  (TL + 10240)
#define TW_L  (TL + 20480)
#define DSM_BYTES 63488

__global__ __launch_bounds__(256) void fused_layer_mma(
        const float* __restrict__ gcb, const float* __restrict__ bib,
        int n, int layer, int inFlag) {
    extern __shared__ __align__(16) char dsm[];
    __shared__ float biasS[128];
    __shared__ float part[64];
    __shared__ float invS[64];

    const int tid  = threadIdx.x;
    const int lane = tid & 31;
    const int w    = tid >> 5;
    const int wm   = w >> 2;
    const int wn   = w & 3;
    const int m0   = wm * 32;
    const int n0   = wn * 32;
    const int nb   = blockIdx.x * 64;
    const int loff = layer * 128;
    const uint32_t sb = smem_to_u32(dsm);

    const float4* egoIn4 = (const float4*)(inFlag ? g_egoB : g_egoA);
    float*        egoOut = inFlag ? g_egoA : g_egoB;

    float4* msgS4 = (float4*)dsm;            // [64][32] float4

    if (tid < 128) biasS[tid] = gcb[loff + tid] + bib[loff + tid];
    if (tid < 64)  part[tid] = 0.f;

    // ==== Phase 1: in-block SpMM — msg for rows nb..nb+63 into msgS ====
#pragma unroll 1
    for (int r = 0; r < 8; ++r) {
        int row = nb + w * 8 + r;
        float4 acc = make_float4(0.f, 0.f, 0.f, 0.f);
        if (row < n) {
            int beg = g_rowptr[row];
            int end = beg + g_cnt[row];
            for (int b = beg; b < end; b += 32) {
                int idx = b + lane;
                int cc = 0; float ww = 0.f;
                if (idx < end) { cc = g_ecol[idx]; ww = g_ewc[idx]; }
                int m = min(32, end - b);
                for (int j = 0; j < m; ++j) {
                    int   c2 = __shfl_sync(0xffffffffu, cc, j);
                    float w2 = __shfl_sync(0xffffffffu, ww, j);
                    float4 v = egoIn4[(size_t)c2 * 32 + lane];
                    acc.x += w2 * v.x; acc.y += w2 * v.y;
                    acc.z += w2 * v.z; acc.w += w2 * v.w;
                }
            }
        }
        msgS4[(w * 8 + r) * 32 + lane] = acc;
    }
    __syncthreads();

    // ==== Phase 2: GEMM over 8 K-chunks of 32 ====
    float acc[2][4][4];
#pragma unroll
    for (int a = 0; a < 2; ++a)
#pragma unroll
        for (int b = 0; b < 4; ++b)
#pragma unroll
            for (int c = 0; c < 4; ++c) acc[a][b][c] = 0.f;

    const unsigned short* wsrc = g_wbf + (size_t)layer * 8 * 2 * 128 * 32;

    for (int c = 0; c < 8; ++c) {
        if (c) __syncthreads();        // protect tiles from previous compute
        // ---- W fill: hi+lo, 1024 uint4 over 256 threads ----
        {
            const uint4* src = (const uint4*)(wsrc + (size_t)(c * 2) * 128 * 32);
#pragma unroll
            for (int i = 0; i < 4; ++i) {
                int idx = tid + 256 * i;
                int h   = idx >> 9;
                int rem = idx & 511;
                int row = rem >> 2;
                int seg = rem & 3;
                uint4 v = src[idx];
                *(uint4*)(dsm + (h ? TW_L : TW_H) + row * (PITCH * 2) + seg * 16) = v;
            }
        }
        // ---- A fill: 512 float4 tasks, msg from smem, split hi/lo ----
#pragma unroll
        for (int i = 0; i < 2; ++i) {
            int idx  = tid + 256 * i;
            int node = idx >> 3;
            int q    = idx & 7;
            int g    = nb + node;
            float4 x;
            if (c < 4) {
                x = msgS4[node * 32 + c * 8 + q];
            } else {
                float4 m = msgS4[node * 32 + (c - 4) * 8 + q];
                float4 e = (g < n) ? egoIn4[(size_t)g * 32 + (c - 4) * 8 + q]
                                   : make_float4(0.f, 0.f, 0.f, 0.f);
                x = make_float4(m.x * e.x, m.y * e.y, m.z * e.z, m.w * e.w);
            }
            uint32_t h01 = bf16x2_of(x.y, x.x);
            uint32_t h23 = bf16x2_of(x.w, x.z);
            float a0 = __uint_as_float(h01 << 16);
            float a1 = __uint_as_float(h01 & 0xffff0000u);
            float a2 = __uint_as_float(h23 << 16);
            float a3 = __uint_as_float(h23 & 0xffff0000u);
            uint32_t l01 = bf16x2_of(x.y - a1, x.x - a0);
            uint32_t l23 = bf16x2_of(x.w - a3, x.z - a2);
            *(uint2*)(dsm + TA_H + node * (PITCH * 2) + q * 8) = make_uint2(h01, h23);
            *(uint2*)(dsm + TA_L + node * (PITCH * 2) + q * 8) = make_uint2(l01, l23);
        }
        __syncthreads();

        // ---- compute: 2 k16 steps ----
#pragma unroll
        for (int kb = 0; kb < 2; ++kb) {
            uint32_t Ah[2][4], Al[2][4], Wh[2][4], Wl[2][4];
            {
                int arow = lane & 15;
                uint32_t aoff = (uint32_t)((lane >> 4) * 16 + kb * 32);
#pragma unroll
                for (int mt = 0; mt < 2; ++mt) {
                    uint32_t ra = sb + TA_H +
                        (uint32_t)(m0 + mt * 16 + arow) * (PITCH * 2) + aoff;
                    ldmx4(Ah[mt], ra);
                    ldmx4(Al[mt], ra + (TA_L - TA_H));
                }
            }
            {
                int g2 = lane >> 3, r2 = lane & 7;
                int wrow = n0 + r2 + ((g2 >> 1) << 3);
                uint32_t woff = (uint32_t)((g2 & 1) * 16 + kb * 32);
#pragma unroll
                for (int nt2 = 0; nt2 < 2; ++nt2) {
                    uint32_t rw = sb + TW_H +
                        (uint32_t)(wrow + nt2 * 16) * (PITCH * 2) + woff;
                    ldmx4(Wh[nt2], rw);
                    ldmx4(Wl[nt2], rw + (TW_L - TW_H));
                }
            }
#pragma unroll
            for (int mt = 0; mt < 2; ++mt) {
#pragma unroll
                for (int nt = 0; nt < 4; ++nt) {
                    const uint32_t* bh = &Wh[nt >> 1][(nt & 1) * 2];
                    const uint32_t* bl = &Wl[nt >> 1][(nt & 1) * 2];
                    mma_bf16(acc[mt][nt], Ah[mt], bh);
                    mma_bf16(acc[mt][nt], Ah[mt], bl);
                    mma_bf16(acc[mt][nt], Al[mt], bh);
                }
            }
        }
    }
    __syncthreads();   // tiles + msgS dead; Vs overlays dsm

    // ==== Phase 3: epilogue ====
    float* Vs = (float*)dsm;          // [64][132]
    float rs[2][2] = {{0.f, 0.f}, {0.f, 0.f}};
#pragma unroll
    for (int mt = 0; mt < 2; ++mt) {
#pragma unroll
        for (int nt = 0; nt < 4; ++nt) {
            int row0 = m0 + mt * 16 + (lane >> 2);
            int col  = n0 + nt * 8 + (lane & 3) * 2;
            float b0 = biasS[col], b1 = biasS[col + 1];
            float x0 = acc[mt][nt][0] + b0;
            float x1 = acc[mt][nt][1] + b1;
            float x2 = acc[mt][nt][2] + b0;
            float x3 = acc[mt][nt][3] + b1;
            x0 = (x0 > 0.f) ? x0 : 0.2f * x0;
            x1 = (x1 > 0.f) ? x1 : 0.2f * x1;
            x2 = (x2 > 0.f) ? x2 : 0.2f * x2;
            x3 = (x3 > 0.f) ? x3 : 0.2f * x3;
            Vs[row0 * 132 + col]           = x0;
            Vs[row0 * 132 + col + 1]       = x1;
            Vs[(row0 + 8) * 132 + col]     = x2;
            Vs[(row0 + 8) * 132 + col + 1] = x3;
            rs[mt][0] += x0 * x0 + x1 * x1;
            rs[mt][1] += x2 * x2 + x3 * x3;
        }
    }
#pragma unroll
    for (int mt = 0; mt < 2; ++mt)
#pragma unroll
        for (int hh = 0; hh < 2; ++hh) {
            float v = rs[mt][hh];
            v += __shfl_xor_sync(0xffffffffu, v, 1);
            v += __shfl_xor_sync(0xffffffffu, v, 2);
            if ((lane & 3) == 0)
                atomicAdd(&part[m0 + mt * 16 + hh * 8 + (lane >> 2)], v);
        }
    __syncthreads();
    if (tid < 64) invS[tid] = 1.0f / fmaxf(sqrtf(part[tid]), 1e-12f);
    __syncthreads();

    for (int i = tid; i < 64 * 32; i += 256) {
        int node = i >> 5, d4 = i & 31;
        int g = nb + node;
        if (g < n) {
            const float* p = Vs + node * 132 + d4 * 4;
            float inv = invS[node];
            float4 v = make_float4(p[0], p[1], p[2], p[3]);
            *(float4*)(egoOut + (size_t)g * 128 + d4 * 4) = v;
            *(float4*)(g_all + (size_t)g * 512 + loff + 128 + d4 * 4) =
                make_float4(v.x * inv, v.y * inv, v.z * inv, v.w * inv);
        }
    }
}

// ---------------------------------------------------------------------------
// Scoring (unchanged).
// ---------------------------------------------------------------------------
__global__ void score(const int* __restrict__ eli, int Q,
                      float* __restrict__ out) {
    int gt = blockIdx.x * blockDim.x + threadIdx.x;
    int q = gt >> 5, lane = gt & 31;
    if (q >= Q) return;
    int s = eli[q];
    int d = eli[Q + q];
    const float4* a = (const float4*)(g_all + (size_t)s * 512);
    const float4* b = (const float4*)(g_all + (size_t)d * 512);
    float acc = 0.f;
#pragma unroll
    for (int j = 0; j < 4; ++j) {
        float4 x = a[lane + 32 * j];
        float4 y = b[lane + 32 * j];
        acc += x.x * y.x + x.y * y.y + x.z * y.z + x.w * y.w;
    }
#pragma unroll
    for (int off = 16; off; off >>= 1)
        acc += __shfl_xor_sync(0xffffffffu, acc, off);
    if (lane == 0) out[q] = acc;
}

// ---------------------------------------------------------------------------
extern "C" void kernel_launch(void* const* d_in, const int* in_sizes, int n_in,
                              void* d_out, int out_size) {
    const int*   ei  = (const int*)d_in[0];
    const int*   eli = (const int*)d_in[1];
    const float* ew  = (const float*)d_in[2];
    const float* emb = (const float*)d_in[3];
    const float* gcw = (const float*)d_in[4];
    const float* gcb = (const float*)d_in[5];
    const float* biw = (const float*)d_in[6];
    const float* bib = (const float*)d_in[7];

    int E = in_sizes[0] / 2;
    int Q = in_sizes[1] / 2;
    int n = in_sizes[3] / 128;
    float* out = (float*)d_out;

    // Idempotent attribute set (not a stream op; capture-safe).
    cudaFuncSetAttribute(fused_layer_mma,
                         cudaFuncAttributeMaxDynamicSharedMemorySize,
                         DSM_BYTES);

    pack_weights<<<(NLYR * 128 * 256 + 255) / 256, 256>>>(gcw, biw);
    init_copy<<<(n * 32 + 255) / 256, 256>>>((const float4*)emb, n);

    csr_hist<<<(E + 255) / 256, 256>>>(ei, E);
    csr_offsets<<<(n + 255) / 256, 256>>>(n);
    csr_scatter<<<(E + 255) / 256, 256>>>(ei, ew, E);

    for (int l = 0; l < NLYR; ++l)
        fused_layer_mma<<<(n + 63) / 64, 256, DSM_BYTES>>>(gcb, bib, n, l,
                                                           l & 1);

    score<<<(int)(((size_t)Q * 32 + 255) / 256), 256>>>(eli, Q, out);
}

// round 13
// speedup vs baseline: 1.0608x; 1.0608x over previous
#include <cuda_runtime.h>
#include <cstdint>

#define NMAX 100000
#define EMAX 1600000
#define NLYR 3

// Device scratch.
__device__ __align__(16) float g_all[(size_t)NMAX * 512];
__device__ __align__(16) float g_ego[(size_t)NMAX * 128];
__device__ __align__(16) float g_msg[(size_t)NMAX * 128];
// Pre-split bf16 weights: [l][chunk 0..7][hi/lo][od 0..127][k 0..31]
__device__ __align__(16) unsigned short g_wbf[NLYR * 8 * 2 * 128 * 32];
// CSR built once per launch.
__device__ int   g_rowptr[NMAX];
__device__ int   g_cnt[NMAX];
__device__ int   g_off[NMAX];
__device__ int   g_total;
__device__ int   g_ecol[EMAX];
__device__ float g_ewc[EMAX];

// ---------------------------------------------------------------------------
__device__ __forceinline__ uint32_t smem_to_u32(const void* p) {
    uint32_t a;
    asm("{ .reg .u64 t; cvta.to.shared.u64 t, %1; cvt.u32.u64 %0, t; }"
        : "=r"(a) : "l"(p));
    return a;
}
__device__ __forceinline__ uint32_t bf16x2_of(float a, float b) {
    uint32_t r;
    asm("cvt.rn.bf16x2.f32 %0, %1, %2;" : "=r"(r) : "f"(a), "f"(b));
    return r;
}
__device__ __forceinline__ void ldmx4(uint32_t* r, uint32_t addr) {
    asm volatile("ldmatrix.sync.aligned.m8n8.x4.shared.b16 {%0,%1,%2,%3}, [%4];"
                 : "=r"(r[0]), "=r"(r[1]), "=r"(r[2]), "=r"(r[3]) : "r"(addr));
}
__device__ __forceinline__ void mma_bf16(float* c, const uint32_t* a,
                                         const uint32_t* b) {
    asm volatile(
        "mma.sync.aligned.m16n8k16.row.col.f32.bf16.bf16.f32 "
        "{%0,%1,%2,%3}, {%4,%5,%6,%7}, {%8,%9}, {%0,%1,%2,%3};"
        : "+f"(c[0]), "+f"(c[1]), "+f"(c[2]), "+f"(c[3])
        : "r"(a[0]), "r"(a[1]), "r"(a[2]), "r"(a[3]), "r"(b[0]), "r"(b[1]));
}
__device__ __forceinline__ void cpasync16(uint32_t daddr, const void* src) {
    asm volatile("cp.async.cg.shared.global [%0], [%1], 16;"
                 :: "r"(daddr), "l"(src) : "memory");
}
#define CP_COMMIT() asm volatile("cp.async.commit_group;" ::: "memory")
#define CP_WAIT1()  asm volatile("cp.async.wait_group 1;" ::: "memory")
#define CP_WAIT0()  asm volatile("cp.async.wait_group 0;" ::: "memory")

// ---------------------------------------------------------------------------
// pack_weights: stacked [gc_w | bi_w] K=256, split to bf16 hi+lo.
// ---------------------------------------------------------------------------
__global__ void pack_weights(const float* __restrict__ gw,
                             const float* __restrict__ bw) {
    int idx = blockIdx.x * blockDim.x + threadIdx.x;
    if (idx >= NLYR * 128 * 256) return;
    int l  = idx >> 15;
    int r  = idx & 32767;
    int od = r >> 8;
    int k  = r & 255;
    float x = (k < 128) ? gw[l * 16384 + od * 128 + k]
                        : bw[l * 16384 + od * 128 + (k - 128)];
    uint32_t h2 = bf16x2_of(x, x);
    float xh = __uint_as_float(h2 & 0xffff0000u);
    uint32_t l2 = bf16x2_of(x - xh, x - xh);
    int c = k >> 5, q = k & 31;
    size_t base = ((size_t)((l * 8 + c) * 2) * 128 + od) * 32 + q;
    g_wbf[base]            = (unsigned short)(h2 >> 16);
    g_wbf[base + 128 * 32] = (unsigned short)(l2 >> 16);
}

// ---------------------------------------------------------------------------
__global__ void init_copy(const float4* __restrict__ emb4, int n) {
    int i = blockIdx.x * blockDim.x + threadIdx.x;
    if (i >= n * 32) return;
    int node = i >> 5, d4 = i & 31;
    float4 v = emb4[i];
    ((float4*)g_all)[(size_t)node * 128 + d4] = v;
    ((float4*)g_ego)[i] = v;
    if (d4 == 0) { g_cnt[node] = 0; g_off[node] = 0; }
    if (i == 0) g_total = 0;
}

// ---------------------------------------------------------------------------
// CSR build (proven path).
// ---------------------------------------------------------------------------
__global__ void csr_hist(const int* __restrict__ ei, int E) {
    int e = blockIdx.x * blockDim.x + threadIdx.x;
    if (e < E) atomicAdd(&g_cnt[ei[e]], 1);
}

__global__ __launch_bounds__(256) void csr_offsets(int n) {
    __shared__ int wbase[8];
    int tid  = threadIdx.x;
    int lane = tid & 31;
    int w    = tid >> 5;
    int i    = blockIdx.x * 256 + tid;
    int cnt  = (i < n) ? g_cnt[i] : 0;

    int pre = cnt;
#pragma unroll
    for (int off = 1; off < 32; off <<= 1) {
        int v = __shfl_up_sync(0xffffffffu, pre, off);
        if (lane >= off) pre += v;
    }
    if (lane == 31) wbase[w] = pre;
    __syncthreads();
    if (w == 0) {
        int orig = (lane < 8) ? wbase[lane] : 0;
        int s = orig;
#pragma unroll
        for (int off = 1; off < 8; off <<= 1) {
            int v = __shfl_up_sync(0xffffffffu, s, off);
            if (lane >= off) s += v;
        }
        int total = __shfl_sync(0xffffffffu, s, 7);
        int base = 0;
        if (lane == 7) base = atomicAdd(&g_total, total);
        base = __shfl_sync(0xffffffffu, base, 7);
        if (lane < 8) wbase[lane] = base + s - orig;
    }
    __syncthreads();
    if (i < n) g_rowptr[i] = wbase[w] + pre - cnt;
}

__global__ void csr_scatter(const int* __restrict__ ei,
                            const float* __restrict__ ew, int E) {
    int e = blockIdx.x * blockDim.x + threadIdx.x;
    if (e >= E) return;
    int row = ei[e];
    int col = ei[E + e];
    int pos = g_rowptr[row] + atomicAdd(&g_off[row], 1);
    g_ecol[pos] = col;
    g_ewc[pos]  = ew[e];
}

// ---------------------------------------------------------------------------
// SpMM via CSR (proven, at gather roof). Separate kernel for full occupancy.
// ---------------------------------------------------------------------------
__global__ void spmm_csr(int n) {
    int gt = blockIdx.x * blockDim.x + threadIdx.x;
    int row = gt >> 5, lane = gt & 31;
    if (row >= n) return;
    int beg = g_rowptr[row];
    int end = beg + g_cnt[row];
    float4 acc = make_float4(0.f, 0.f, 0.f, 0.f);
    for (int b = beg; b < end; b += 32) {
        int idx = b + lane;
        int c = 0; float w = 0.f;
        if (idx < end) { c = g_ecol[idx]; w = g_ewc[idx]; }
        int m = min(32, end - b);
        for (int j = 0; j < m; ++j) {
            int   cc = __shfl_sync(0xffffffffu, c, j);
            float ww = __shfl_sync(0xffffffffu, w, j);
            float4 v = ((const float4*)g_ego)[(size_t)cc * 32 + lane];
            acc.x += ww * v.x; acc.y += ww * v.y;
            acc.z += ww * v.z; acc.w += ww * v.w;
        }
    }
    ((float4*)g_msg)[(size_t)row * 32 + lane] = acc;
}

// ---------------------------------------------------------------------------
// Fused layer via warp-level split-bf16 HMMA, pipelined fills:
//   W: cp.async double-buffered; A: register-prefetch (R9 pattern).
//   C[64 nodes][128 od] = A[64][256] * W[128][256]^T, A = [msg | ego*msg]
//   3 terms: Ah*Wh + Ah*Wl + Al*Wh, fp32 register accumulate.
// Dynamic smem (51200 B):
//   [0:5120)       A hi   [64][PITCH]
//   [5120:10240)   A lo
//   [10240:30720)  W buf0 hi/lo (10240 each)
//   [30720:51200)  W buf1 hi/lo
//   epilogue overlays Vs[64][132] fp32 at offset 0.
// ---------------------------------------------------------------------------
#define PITCH 40                   // shorts per row (80 B), ldmatrix-safe
#define TA_H  0
#define TA_L  5120
#define TW0   10240
#define TW1   30720
#define DSM_BYTES 51200

__global__ __launch_bounds__(256, 2) void fused_layer_mma(
        const float* __restrict__ gcb, const float* __restrict__ bib,
        int n, int layer) {
    extern __shared__ __align__(16) char dsm[];
    __shared__ float biasS[128];
    __shared__ float part[64];
    __shared__ float invS[64];

    const int tid  = threadIdx.x;
    const int lane = tid & 31;
    const int w    = tid >> 5;
    const int wm   = w >> 2;
    const int wn   = w & 3;
    const int m0   = wm * 32;
    const int n0   = wn * 32;
    const int nb   = blockIdx.x * 64;
    const int loff = layer * 128;
    const uint32_t sb = smem_to_u32(dsm);

    if (tid < 128) biasS[tid] = gcb[loff + tid] + bib[loff + tid];
    if (tid < 64)  part[tid] = 0.f;

    float acc[2][4][4];
#pragma unroll
    for (int a = 0; a < 2; ++a)
#pragma unroll
        for (int b = 0; b < 4; ++b)
#pragma unroll
            for (int c = 0; c < 4; ++c) acc[a][b][c] = 0.f;

    const unsigned short* wsrc = g_wbf + (size_t)layer * 8 * 2 * 128 * 32;

    // A-fill constants: 2 tasks per thread (idx = tid, tid+256)
    const int an0 = tid >> 3;            // node of task 0
    const int aq  = tid & 7;             // float4 quad
    const int an1 = (tid + 256) >> 3;    // node of task 1
    const bool ok0 = (nb + an0) < n;
    const bool ok1 = (nb + an1) < n;
    const float4* msg4 = (const float4*)g_msg;
    const float4* ego4 = (const float4*)g_ego;
    const float4 z4 = make_float4(0.f, 0.f, 0.f, 0.f);

    // ---- prologue: cp.async W chunk 0 -> buf0; load A chunk 0 regs ----
    {
        const uint4* src = (const uint4*)wsrc;
#pragma unroll
        for (int i = 0; i < 4; ++i) {
            int idx = tid + 256 * i;
            int h   = idx >> 9;
            int rem = idx & 511;
            int row = rem >> 2;
            int seg = rem & 3;
            cpasync16(sb + TW0 + h * 10240 + row * (PITCH * 2) + seg * 16,
                      src + idx);
        }
        CP_COMMIT();
    }
    float4 pm0, pm1, pe0, pe1;
    pm0 = ok0 ? msg4[(size_t)(nb + an0) * 32 + aq] : z4;
    pm1 = ok1 ? msg4[(size_t)(nb + an1) * 32 + aq] : z4;
    pe0 = z4; pe1 = z4;

    for (int c = 0; c < 8; ++c) {
        // ---- STS A chunk c from prefetch regs (split hi/lo) ----
        {
            float4 xs[2];
            if (c < 4) { xs[0] = pm0; xs[1] = pm1; }
            else {
                xs[0] = make_float4(pm0.x * pe0.x, pm0.y * pe0.y,
                                    pm0.z * pe0.z, pm0.w * pe0.w);
                xs[1] = make_float4(pm1.x * pe1.x, pm1.y * pe1.y,
                                    pm1.z * pe1.z, pm1.w * pe1.w);
            }
#pragma unroll
            for (int i = 0; i < 2; ++i) {
                float4 x = xs[i];
                int node = i ? an1 : an0;
                uint32_t h01 = bf16x2_of(x.y, x.x);
                uint32_t h23 = bf16x2_of(x.w, x.z);
                float a0 = __uint_as_float(h01 << 16);
                float a1 = __uint_as_float(h01 & 0xffff0000u);
                float a2 = __uint_as_float(h23 << 16);
                float a3 = __uint_as_float(h23 & 0xffff0000u);
                uint32_t l01 = bf16x2_of(x.y - a1, x.x - a0);
                uint32_t l23 = bf16x2_of(x.w - a3, x.z - a2);
                *(uint2*)(dsm + TA_H + node * (PITCH * 2) + aq * 8) =
                    make_uint2(h01, h23);
                *(uint2*)(dsm + TA_L + node * (PITCH * 2) + aq * 8) =
                    make_uint2(l01, l23);
            }
        }

        // ---- issue next chunk's W cp.async + A LDGs ----
        if (c < 7) {
            int nc = c + 1;
            const uint4* src = (const uint4*)(wsrc + (size_t)(nc * 2) * 128 * 32);
            uint32_t base = sb + ((nc & 1) ? TW1 : TW0);
#pragma unroll
            for (int i = 0; i < 4; ++i) {
                int idx = tid + 256 * i;
                int h   = idx >> 9;
                int rem = idx & 511;
                int row = rem >> 2;
                int seg = rem & 3;
                cpasync16(base + h * 10240 + row * (PITCH * 2) + seg * 16,
                          src + idx);
            }
            CP_COMMIT();
            if (nc < 4) {
                pm0 = ok0 ? msg4[(size_t)(nb + an0) * 32 + nc * 8 + aq] : z4;
                pm1 = ok1 ? msg4[(size_t)(nb + an1) * 32 + nc * 8 + aq] : z4;
            } else {
                int kk = (nc - 4) * 8 + aq;
                pm0 = ok0 ? msg4[(size_t)(nb + an0) * 32 + kk] : z4;
                pm1 = ok1 ? msg4[(size_t)(nb + an1) * 32 + kk] : z4;
                pe0 = ok0 ? ego4[(size_t)(nb + an0) * 32 + kk] : z4;
                pe1 = ok1 ? ego4[(size_t)(nb + an1) * 32 + kk] : z4;
            }
            CP_WAIT1();     // chunk c's W group complete
        } else {
            CP_WAIT0();
        }
        __syncthreads();

        // ---- compute chunk c: 2 k16 steps ----
        const uint32_t wb = sb + ((c & 1) ? TW1 : TW0);
#pragma unroll
        for (int kb = 0; kb < 2; ++kb) {
            uint32_t Ah[2][4], Al[2][4], Wh[2][4], Wl[2][4];
            {
                int arow = lane & 15;
                uint32_t aoff = (uint32_t)((lane >> 4) * 16 + kb * 32);
#pragma unroll
                for (int mt = 0; mt < 2; ++mt) {
                    uint32_t ra = sb + TA_H +
                        (uint32_t)(m0 + mt * 16 + arow) * (PITCH * 2) + aoff;
                    ldmx4(Ah[mt], ra);
                    ldmx4(Al[mt], ra + (TA_L - TA_H));
                }
            }
            {
                int g2 = lane >> 3, r2 = lane & 7;
                int wrow = n0 + r2 + ((g2 >> 1) << 3);
                uint32_t woff = (uint32_t)((g2 & 1) * 16 + kb * 32);
#pragma unroll
                for (int nt2 = 0; nt2 < 2; ++nt2) {
                    uint32_t rw = wb +
                        (uint32_t)(wrow + nt2 * 16) * (PITCH * 2) + woff;
                    ldmx4(Wh[nt2], rw);
                    ldmx4(Wl[nt2], rw + 10240);
                }
            }
#pragma unroll
            for (int mt = 0; mt < 2; ++mt) {
#pragma unroll
                for (int nt = 0; nt < 4; ++nt) {
                    const uint32_t* bh = &Wh[nt >> 1][(nt & 1) * 2];
                    const uint32_t* bl = &Wl[nt >> 1][(nt & 1) * 2];
                    mma_bf16(acc[mt][nt], Ah[mt], bh);
                    mma_bf16(acc[mt][nt], Ah[mt], bl);
                    mma_bf16(acc[mt][nt], Al[mt], bh);
                }
            }
        }
        __syncthreads();   // A tile free for next STS
    }

    // ==== epilogue ====
    float* Vs = (float*)dsm;          // [64][132] overlays tiles
    float rs[2][2] = {{0.f, 0.f}, {0.f, 0.f}};
#pragma unroll
    for (int mt = 0; mt < 2; ++mt) {
#pragma unroll
        for (int nt = 0; nt < 4; ++nt) {
            int row0 = m0 + mt * 16 + (lane >> 2);
            int col  = n0 + nt * 8 + (lane & 3) * 2;
            float b0 = biasS[col], b1 = biasS[col + 1];
            float x0 = acc[mt][nt][0] + b0;
            float x1 = acc[mt][nt][1] + b1;
            float x2 = acc[mt][nt][2] + b0;
            float x3 = acc[mt][nt][3] + b1;
            x0 = (x0 > 0.f) ? x0 : 0.2f * x0;
            x1 = (x1 > 0.f) ? x1 : 0.2f * x1;
            x2 = (x2 > 0.f) ? x2 : 0.2f * x2;
            x3 = (x3 > 0.f) ? x3 : 0.2f * x3;
            Vs[row0 * 132 + col]           = x0;
            Vs[row0 * 132 + col + 1]       = x1;
            Vs[(row0 + 8) * 132 + col]     = x2;
            Vs[(row0 + 8) * 132 + col + 1] = x3;
            rs[mt][0] += x0 * x0 + x1 * x1;
            rs[mt][1] += x2 * x2 + x3 * x3;
        }
    }
#pragma unroll
    for (int mt = 0; mt < 2; ++mt)
#pragma unroll
        for (int hh = 0; hh < 2; ++hh) {
            float v = rs[mt][hh];
            v += __shfl_xor_sync(0xffffffffu, v, 1);
            v += __shfl_xor_sync(0xffffffffu, v, 2);
            if ((lane & 3) == 0)
                atomicAdd(&part[m0 + mt * 16 + hh * 8 + (lane >> 2)], v);
        }
    __syncthreads();
    if (tid < 64) invS[tid] = 1.0f / fmaxf(sqrtf(part[tid]), 1e-12f);
    __syncthreads();

    for (int i = tid; i < 64 * 32; i += 256) {
        int node = i >> 5, d4 = i & 31;
        int g = nb + node;
        if (g < n) {
            const float* p = Vs + node * 132 + d4 * 4;
            float inv = invS[node];
            float4 v = make_float4(p[0], p[1], p[2], p[3]);
            *(float4*)(g_ego + (size_t)g * 128 + d4 * 4) = v;
            *(float4*)(g_all + (size_t)g * 512 + loff + 128 + d4 * 4) =
                make_float4(v.x * inv, v.y * inv, v.z * inv, v.w * inv);
        }
    }
}

// ---------------------------------------------------------------------------
// Scoring (unchanged).
// ---------------------------------------------------------------------------
__global__ void score(const int* __restrict__ eli, int Q,
                      float* __restrict__ out) {
    int gt = blockIdx.x * blockDim.x + threadIdx.x;
    int q = gt >> 5, lane = gt & 31;
    if (q >= Q) return;
    int s = eli[q];
    int d = eli[Q + q];
    const float4* a = (const float4*)(g_all + (size_t)s * 512);
    const float4* b = (const float4*)(g_all + (size_t)d * 512);
    float acc = 0.f;
#pragma unroll
    for (int j = 0; j < 4; ++j) {
        float4 x = a[lane + 32 * j];
        float4 y = b[lane + 32 * j];
        acc += x.x * y.x + x.y * y.y + x.z * y.z + x.w * y.w;
    }
#pragma unroll
    for (int off = 16; off; off >>= 1)
        acc += __shfl_xor_sync(0xffffffffu, acc, off);
    if (lane == 0) out[q] = acc;
}

// ---------------------------------------------------------------------------
extern "C" void kernel_launch(void* const* d_in, const int* in_sizes, int n_in,
                              void* d_out, int out_size) {
    const int*   ei  = (const int*)d_in[0];
    const int*   eli = (const int*)d_in[1];
    const float* ew  = (const float*)d_in[2];
    const float* emb = (const float*)d_in[3];
    const float* gcw = (const float*)d_in[4];
    const float* gcb = (const float*)d_in[5];
    const float* biw = (const float*)d_in[6];
    const float* bib = (const float*)d_in[7];

    int E = in_sizes[0] / 2;
    int Q = in_sizes[1] / 2;
    int n = in_sizes[3] / 128;
    float* out = (float*)d_out;

    // Idempotent attribute set (not a stream op; capture-safe).
    cudaFuncSetAttribute(fused_layer_mma,
                         cudaFuncAttributeMaxDynamicSharedMemorySize,
                         DSM_BYTES);

    pack_weights<<<(NLYR * 128 * 256 + 255) / 256, 256>>>(gcw, biw);
    init_copy<<<(n * 32 + 255) / 256, 256>>>((const float4*)emb, n);

    csr_hist<<<(E + 255) / 256, 256>>>(ei, E);
    csr_offsets<<<(n + 255) / 256, 256>>>(n);
    csr_scatter<<<(E + 255) / 256, 256>>>(ei, ew, E);

    for (int l = 0; l < NLYR; ++l) {
        spmm_csr<<<(int)(((size_t)n * 32 + 255) / 256), 256>>>(n);
        fused_layer_mma<<<(n + 63) / 64, 256, DSM_BYTES>>>(gcb, bib, n, l);
    }

    score<<<(int)(((size_t)Q * 32 + 255) / 256), 256>>>(eli, Q, out);
}

// round 14
// speedup vs baseline: 1.1035x; 1.0403x over previous
#include <cuda_runtime.h>
#include <cuda_fp16.h>
#include <cstdint>

#define NMAX 100000
#define EMAX 1600000
#define NLYR 3

// Device scratch.
__device__ __align__(16) float g_all[(size_t)NMAX * 512];
__device__ __align__(16) float g_ego[(size_t)NMAX * 128];    // fp32 ego (GEMM product term)
__device__ __align__(16) __half g_egoH[(size_t)NMAX * 128];  // fp16 ego (SpMM gather)
__device__ __align__(16) float g_msg[(size_t)NMAX * 128];
// Pre-split bf16 weights: [l][chunk 0..7][hi/lo][od 0..127][k 0..31]
__device__ __align__(16) unsigned short g_wbf[NLYR * 8 * 2 * 128 * 32];
// CSR built once per launch.
__device__ int   g_rowptr[NMAX];
__device__ int   g_cnt[NMAX];
__device__ int   g_off[NMAX];
__device__ int   g_total;
__device__ int   g_ecol[EMAX];
__device__ float g_ewc[EMAX];

// ---------------------------------------------------------------------------
__device__ __forceinline__ uint32_t smem_to_u32(const void* p) {
    uint32_t a;
    asm("{ .reg .u64 t; cvta.to.shared.u64 t, %1; cvt.u32.u64 %0, t; }"
        : "=r"(a) : "l"(p));
    return a;
}
__device__ __forceinline__ uint32_t bf16x2_of(float a, float b) {
    uint32_t r;
    asm("cvt.rn.bf16x2.f32 %0, %1, %2;" : "=r"(r) : "f"(a), "f"(b));
    return r;
}
__device__ __forceinline__ void ldmx4(uint32_t* r, uint32_t addr) {
    asm volatile("ldmatrix.sync.aligned.m8n8.x4.shared.b16 {%0,%1,%2,%3}, [%4];"
                 : "=r"(r[0]), "=r"(r[1]), "=r"(r[2]), "=r"(r[3]) : "r"(addr));
}
__device__ __forceinline__ void mma_bf16(float* c, const uint32_t* a,
                                         const uint32_t* b) {
    asm volatile(
        "mma.sync.aligned.m16n8k16.row.col.f32.bf16.bf16.f32 "
        "{%0,%1,%2,%3}, {%4,%5,%6,%7}, {%8,%9}, {%0,%1,%2,%3};"
        : "+f"(c[0]), "+f"(c[1]), "+f"(c[2]), "+f"(c[3])
        : "r"(a[0]), "r"(a[1]), "r"(a[2]), "r"(a[3]), "r"(b[0]), "r"(b[1]));
}
__device__ __forceinline__ void cpasync16(uint32_t daddr, const void* src) {
    asm volatile("cp.async.cg.shared.global [%0], [%1], 16;"
                 :: "r"(daddr), "l"(src) : "memory");
}
#define CP_COMMIT() asm volatile("cp.async.commit_group;" ::: "memory")
#define CP_WAIT1()  asm volatile("cp.async.wait_group 1;" ::: "memory")
#define CP_WAIT0()  asm volatile("cp.async.wait_group 0;" ::: "memory")

// pack float4 -> 2x half2 (uint2)
__device__ __forceinline__ uint2 f4_to_h4(float4 v) {
    __half2 a = __floats2half2_rn(v.x, v.y);
    __half2 b = __floats2half2_rn(v.z, v.w);
    uint2 r;
    r.x = *reinterpret_cast<uint32_t*>(&a);
    r.y = *reinterpret_cast<uint32_t*>(&b);
    return r;
}
__device__ __forceinline__ float4 h4_to_f4(uint2 u) {
    __half2 a = *reinterpret_cast<__half2*>(&u.x);
    __half2 b = *reinterpret_cast<__half2*>(&u.y);
    float2 f0 = __half22float2(a);
    float2 f1 = __half22float2(b);
    return make_float4(f0.x, f0.y, f1.x, f1.y);
}

// ---------------------------------------------------------------------------
// pack_weights: stacked [gc_w | bi_w] K=256, split to bf16 hi+lo.
// ---------------------------------------------------------------------------
__global__ void pack_weights(const float* __restrict__ gw,
                             const float* __restrict__ bw) {
    int idx = blockIdx.x * blockDim.x + threadIdx.x;
    if (idx >= NLYR * 128 * 256) return;
    int l  = idx >> 15;
    int r  = idx & 32767;
    int od = r >> 8;
    int k  = r & 255;
    float x = (k < 128) ? gw[l * 16384 + od * 128 + k]
                        : bw[l * 16384 + od * 128 + (k - 128)];
    uint32_t h2 = bf16x2_of(x, x);
    float xh = __uint_as_float(h2 & 0xffff0000u);
    uint32_t l2 = bf16x2_of(x - xh, x - xh);
    int c = k >> 5, q = k & 31;
    size_t base = ((size_t)((l * 8 + c) * 2) * 128 + od) * 32 + q;
    g_wbf[base]            = (unsigned short)(h2 >> 16);
    g_wbf[base + 128 * 32] = (unsigned short)(l2 >> 16);
}

// ---------------------------------------------------------------------------
__global__ void init_copy(const float4* __restrict__ emb4, int n) {
    int i = blockIdx.x * blockDim.x + threadIdx.x;
    if (i >= n * 32) return;
    int node = i >> 5, d4 = i & 31;
    float4 v = emb4[i];
    ((float4*)g_all)[(size_t)node * 128 + d4] = v;
    ((float4*)g_ego)[i] = v;
    ((uint2*)g_egoH)[i] = f4_to_h4(v);
    if (d4 == 0) { g_cnt[node] = 0; g_off[node] = 0; }
    if (i == 0) g_total = 0;
}

// ---------------------------------------------------------------------------
// CSR build (proven path).
// ---------------------------------------------------------------------------
__global__ void csr_hist(const int* __restrict__ ei, int E) {
    int e = blockIdx.x * blockDim.x + threadIdx.x;
    if (e < E) atomicAdd(&g_cnt[ei[e]], 1);
}

__global__ __launch_bounds__(256) void csr_offsets(int n) {
    __shared__ int wbase[8];
    int tid  = threadIdx.x;
    int lane = tid & 31;
    int w    = tid >> 5;
    int i    = blockIdx.x * 256 + tid;
    int cnt  = (i < n) ? g_cnt[i] : 0;

    int pre = cnt;
#pragma unroll
    for (int off = 1; off < 32; off <<= 1) {
        int v = __shfl_up_sync(0xffffffffu, pre, off);
        if (lane >= off) pre += v;
    }
    if (lane == 31) wbase[w] = pre;
    __syncthreads();
    if (w == 0) {
        int orig = (lane < 8) ? wbase[lane] : 0;
        int s = orig;
#pragma unroll
        for (int off = 1; off < 8; off <<= 1) {
            int v = __shfl_up_sync(0xffffffffu, s, off);
            if (lane >= off) s += v;
        }
        int total = __shfl_sync(0xffffffffu, s, 7);
        int base = 0;
        if (lane == 7) base = atomicAdd(&g_total, total);
        base = __shfl_sync(0xffffffffu, base, 7);
        if (lane < 8) wbase[lane] = base + s - orig;
    }
    __syncthreads();
    if (i < n) g_rowptr[i] = wbase[w] + pre - cnt;
}

__global__ void csr_scatter(const int* __restrict__ ei,
                            const float* __restrict__ ew, int E) {
    int e = blockIdx.x * blockDim.x + threadIdx.x;
    if (e >= E) return;
    int row = ei[e];
    int col = ei[E + e];
    int pos = g_rowptr[row] + atomicAdd(&g_off[row], 1);
    g_ecol[pos] = col;
    g_ewc[pos]  = ew[e];
}

// ---------------------------------------------------------------------------
// SpMM via CSR, fp16 ego gather (256 B/row — half the fp32 traffic).
// One warp per row; lane covers dims 4*lane..4*lane+3; fp32 accumulate.
// ---------------------------------------------------------------------------
__global__ void spmm_csr(int n) {
    int gt = blockIdx.x * blockDim.x + threadIdx.x;
    int row = gt >> 5, lane = gt & 31;
    if (row >= n) return;
    int beg = g_rowptr[row];
    int end = beg + g_cnt[row];
    float4 acc = make_float4(0.f, 0.f, 0.f, 0.f);
    const uint2* egoH2 = (const uint2*)g_egoH;
    for (int b = beg; b < end; b += 32) {
        int idx = b + lane;
        int c = 0; float w = 0.f;
        if (idx < end) { c = g_ecol[idx]; w = g_ewc[idx]; }
        int m = min(32, end - b);
        for (int j = 0; j < m; ++j) {
            int   cc = __shfl_sync(0xffffffffu, c, j);
            float ww = __shfl_sync(0xffffffffu, w, j);
            float4 v = h4_to_f4(egoH2[(size_t)cc * 32 + lane]);
            acc.x += ww * v.x; acc.y += ww * v.y;
            acc.z += ww * v.z; acc.w += ww * v.w;
        }
    }
    ((float4*)g_msg)[(size_t)row * 32 + lane] = acc;
}

// ---------------------------------------------------------------------------
// Fused layer via warp-level split-bf16 HMMA, pipelined fills (R13, proven):
//   W: cp.async double-buffered; A: register-prefetch.
//   C[64 nodes][128 od] = A[64][256] * W[128][256]^T, A = [msg | ego*msg]
//   3 terms: Ah*Wh + Ah*Wl + Al*Wh, fp32 register accumulate.
// ---------------------------------------------------------------------------
#define PITCH 40                   // shorts per row (80 B), ldmatrix-safe
#define TA_H  0
#define TA_L  5120
#define TW0   10240
#define TW1   30720
#define DSM_BYTES 51200

__global__ __launch_bounds__(256, 2) void fused_layer_mma(
        const float* __restrict__ gcb, const float* __restrict__ bib,
        int n, int layer) {
    extern __shared__ __align__(16) char dsm[];
    __shared__ float biasS[128];
    __shared__ float part[64];
    __shared__ float invS[64];

    const int tid  = threadIdx.x;
    const int lane = tid & 31;
    const int w    = tid >> 5;
    const int wm   = w >> 2;
    const int wn   = w & 3;
    const int m0   = wm * 32;
    const int n0   = wn * 32;
    const int nb   = blockIdx.x * 64;
    const int loff = layer * 128;
    const uint32_t sb = smem_to_u32(dsm);

    if (tid < 128) biasS[tid] = gcb[loff + tid] + bib[loff + tid];
    if (tid < 64)  part[tid] = 0.f;

    float acc[2][4][4];
#pragma unroll
    for (int a = 0; a < 2; ++a)
#pragma unroll
        for (int b = 0; b < 4; ++b)
#pragma unroll
            for (int c = 0; c < 4; ++c) acc[a][b][c] = 0.f;

    const unsigned short* wsrc = g_wbf + (size_t)layer * 8 * 2 * 128 * 32;

    const int an0 = tid >> 3;
    const int aq  = tid & 7;
    const int an1 = (tid + 256) >> 3;
    const bool ok0 = (nb + an0) < n;
    const bool ok1 = (nb + an1) < n;
    const float4* msg4 = (const float4*)g_msg;
    const float4* ego4 = (const float4*)g_ego;
    const float4 z4 = make_float4(0.f, 0.f, 0.f, 0.f);

    // ---- prologue: cp.async W chunk 0 -> buf0; load A chunk 0 regs ----
    {
        const uint4* src = (const uint4*)wsrc;
#pragma unroll
        for (int i = 0; i < 4; ++i) {
            int idx = tid + 256 * i;
            int h   = idx >> 9;
            int rem = idx & 511;
            int row = rem >> 2;
            int seg = rem & 3;
            cpasync16(sb + TW0 + h * 10240 + row * (PITCH * 2) + seg * 16,
                      src + idx);
        }
        CP_COMMIT();
    }
    float4 pm0, pm1, pe0, pe1;
    pm0 = ok0 ? msg4[(size_t)(nb + an0) * 32 + aq] : z4;
    pm1 = ok1 ? msg4[(size_t)(nb + an1) * 32 + aq] : z4;
    pe0 = z4; pe1 = z4;

    for (int c = 0; c < 8; ++c) {
        // ---- STS A chunk c from prefetch regs (split hi/lo) ----
        {
            float4 xs[2];
            if (c < 4) { xs[0] = pm0; xs[1] = pm1; }
            else {
                xs[0] = make_float4(pm0.x * pe0.x, pm0.y * pe0.y,
                                    pm0.z * pe0.z, pm0.w * pe0.w);
                xs[1] = make_float4(pm1.x * pe1.x, pm1.y * pe1.y,
                                    pm1.z * pe1.z, pm1.w * pe1.w);
            }
#pragma unroll
            for (int i = 0; i < 2; ++i) {
                float4 x = xs[i];
                int node = i ? an1 : an0;
                uint32_t h01 = bf16x2_of(x.y, x.x);
                uint32_t h23 = bf16x2_of(x.w, x.z);
                float a0 = __uint_as_float(h01 << 16);
                float a1 = __uint_as_float(h01 & 0xffff0000u);
                float a2 = __uint_as_float(h23 << 16);
                float a3 = __uint_as_float(h23 & 0xffff0000u);
                uint32_t l01 = bf16x2_of(x.y - a1, x.x - a0);
                uint32_t l23 = bf16x2_of(x.w - a3, x.z - a2);
                *(uint2*)(dsm + TA_H + node * (PITCH * 2) + aq * 8) =
                    make_uint2(h01, h23);
                *(uint2*)(dsm + TA_L + node * (PITCH * 2) + aq * 8) =
                    make_uint2(l01, l23);
            }
        }

        // ---- issue next chunk's W cp.async + A LDGs ----
        if (c < 7) {
            int nc = c + 1;
            const uint4* src = (const uint4*)(wsrc + (size_t)(nc * 2) * 128 * 32);
            uint32_t base = sb + ((nc & 1) ? TW1 : TW0);
#pragma unroll
            for (int i = 0; i < 4; ++i) {
                int idx = tid + 256 * i;
                int h   = idx >> 9;
                int rem = idx & 511;
                int row = rem >> 2;
                int seg = rem & 3;
                cpasync16(base + h * 10240 + row * (PITCH * 2) + seg * 16,
                          src + idx);
            }
            CP_COMMIT();
            if (nc < 4) {
                pm0 = ok0 ? msg4[(size_t)(nb + an0) * 32 + nc * 8 + aq] : z4;
                pm1 = ok1 ? msg4[(size_t)(nb + an1) * 32 + nc * 8 + aq] : z4;
            } else {
                int kk = (nc - 4) * 8 + aq;
                pm0 = ok0 ? msg4[(size_t)(nb + an0) * 32 + kk] : z4;
                pm1 = ok1 ? msg4[(size_t)(nb + an1) * 32 + kk] : z4;
                pe0 = ok0 ? ego4[(size_t)(nb + an0) * 32 + kk] : z4;
                pe1 = ok1 ? ego4[(size_t)(nb + an1) * 32 + kk] : z4;
            }
            CP_WAIT1();
        } else {
            CP_WAIT0();
        }
        __syncthreads();

        // ---- compute chunk c: 2 k16 steps ----
        const uint32_t wb = sb + ((c & 1) ? TW1 : TW0);
#pragma unroll
        for (int kb = 0; kb < 2; ++kb) {
            uint32_t Ah[2][4], Al[2][4], Wh[2][4], Wl[2][4];
            {
                int arow = lane & 15;
                uint32_t aoff = (uint32_t)((lane >> 4) * 16 + kb * 32);
#pragma unroll
                for (int mt = 0; mt < 2; ++mt) {
                    uint32_t ra = sb + TA_H +
                        (uint32_t)(m0 + mt * 16 + arow) * (PITCH * 2) + aoff;
                    ldmx4(Ah[mt], ra);
                    ldmx4(Al[mt], ra + (TA_L - TA_H));
                }
            }
            {
                int g2 = lane >> 3, r2 = lane & 7;
                int wrow = n0 + r2 + ((g2 >> 1) << 3);
                uint32_t woff = (uint32_t)((g2 & 1) * 16 + kb * 32);
#pragma unroll
                for (int nt2 = 0; nt2 < 2; ++nt2) {
                    uint32_t rw = wb +
                        (uint32_t)(wrow + nt2 * 16) * (PITCH * 2) + woff;
                    ldmx4(Wh[nt2], rw);
                    ldmx4(Wl[nt2], rw + 10240);
                }
            }
#pragma unroll
            for (int mt = 0; mt < 2; ++mt) {
#pragma unroll
                for (int nt = 0; nt < 4; ++nt) {
                    const uint32_t* bh = &Wh[nt >> 1][(nt & 1) * 2];
                    const uint32_t* bl = &Wl[nt >> 1][(nt & 1) * 2];
                    mma_bf16(acc[mt][nt], Ah[mt], bh);
                    mma_bf16(acc[mt][nt], Ah[mt], bl);
                    mma_bf16(acc[mt][nt], Al[mt], bh);
                }
            }
        }
        __syncthreads();
    }

    // ==== epilogue ====
    float* Vs = (float*)dsm;          // [64][132] overlays tiles
    float rs[2][2] = {{0.f, 0.f}, {0.f, 0.f}};
#pragma unroll
    for (int mt = 0; mt < 2; ++mt) {
#pragma unroll
        for (int nt = 0; nt < 4; ++nt) {
            int row0 = m0 + mt * 16 + (lane >> 2);
            int col  = n0 + nt * 8 + (lane & 3) * 2;
            float b0 = biasS[col], b1 = biasS[col + 1];
            float x0 = acc[mt][nt][0] + b0;
            float x1 = acc[mt][nt][1] + b1;
            float x2 = acc[mt][nt][2] + b0;
            float x3 = acc[mt][nt][3] + b1;
            x0 = (x0 > 0.f) ? x0 : 0.2f * x0;
            x1 = (x1 > 0.f) ? x1 : 0.2f * x1;
            x2 = (x2 > 0.f) ? x2 : 0.2f * x2;
            x3 = (x3 > 0.f) ? x3 : 0.2f * x3;
            Vs[row0 * 132 + col]           = x0;
            Vs[row0 * 132 + col + 1]       = x1;
            Vs[(row0 + 8) * 132 + col]     = x2;
            Vs[(row0 + 8) * 132 + col + 1] = x3;
            rs[mt][0] += x0 * x0 + x1 * x1;
            rs[mt][1] += x2 * x2 + x3 * x3;
        }
    }
#pragma unroll
    for (int mt = 0; mt < 2; ++mt)
#pragma unroll
        for (int hh = 0; hh < 2; ++hh) {
            float v = rs[mt][hh];
            v += __shfl_xor_sync(0xffffffffu, v, 1);
            v += __shfl_xor_sync(0xffffffffu, v, 2);
            if ((lane & 3) == 0)
                atomicAdd(&part[m0 + mt * 16 + hh * 8 + (lane >> 2)], v);
        }
    __syncthreads();
    if (tid < 64) invS[tid] = 1.0f / fmaxf(sqrtf(part[tid]), 1e-12f);
    __syncthreads();

    for (int i = tid; i < 64 * 32; i += 256) {
        int node = i >> 5, d4 = i & 31;
        int g = nb + node;
        if (g < n) {
            const float* p = Vs + node * 132 + d4 * 4;
            float inv = invS[node];
            float4 v = make_float4(p[0], p[1], p[2], p[3]);
            *(float4*)(g_ego + (size_t)g * 128 + d4 * 4) = v;
            ((uint2*)g_egoH)[(size_t)g * 32 + d4] = f4_to_h4(v);
            *(float4*)(g_all + (size_t)g * 512 + loff + 128 + d4 * 4) =
                make_float4(v.x * inv, v.y * inv, v.z * inv, v.w * inv);
        }
    }
}

// ---------------------------------------------------------------------------
// Scoring (unchanged).
// ---------------------------------------------------------------------------
__global__ void score(const int* __restrict__ eli, int Q,
                      float* __restrict__ out) {
    int gt = blockIdx.x * blockDim.x + threadIdx.x;
    int q = gt >> 5, lane = gt & 31;
    if (q >= Q) return;
    int s = eli[q];
    int d = eli[Q + q];
    const float4* a = (const float4*)(g_all + (size_t)s * 512);
    const float4* b = (const float4*)(g_all + (size_t)d * 512);
    float acc = 0.f;
#pragma unroll
    for (int j = 0; j < 4; ++j) {
        float4 x = a[lane + 32 * j];
        float4 y = b[lane + 32 * j];
        acc += x.x * y.x + x.y * y.y + x.z * y.z + x.w * y.w;
    }
#pragma unroll
    for (int off = 16; off; off >>= 1)
        acc += __shfl_xor_sync(0xffffffffu, acc, off);
    if (lane == 0) out[q] = acc;
}

// ---------------------------------------------------------------------------
extern "C" void kernel_launch(void* const* d_in, const int* in_sizes, int n_in,
                              void* d_out, int out_size) {
    const int*   ei  = (const int*)d_in[0];
    const int*   eli = (const int*)d_in[1];
    const float* ew  = (const float*)d_in[2];
    const float* emb = (const float*)d_in[3];
    const float* gcw = (const float*)d_in[4];
    const float* gcb = (const float*)d_in[5];
    const float* biw = (const float*)d_in[6];
    const float* bib = (const float*)d_in[7];

    int E = in_sizes[0] / 2;
    int Q = in_sizes[1] / 2;
    int n = in_sizes[3] / 128;
    float* out = (float*)d_out;

    // Idempotent attribute set (not a stream op; capture-safe).
    cudaFuncSetAttribute(fused_layer_mma,
                         cudaFuncAttributeMaxDynamicSharedMemorySize,
                         DSM_BYTES);

    pack_weights<<<(NLYR * 128 * 256 + 255) / 256, 256>>>(gcw, biw);
    init_copy<<<(n * 32 + 255) / 256, 256>>>((const float4*)emb, n);

    csr_hist<<<(E + 255) / 256, 256>>>(ei, E);
    csr_offsets<<<(n + 255) / 256, 256>>>(n);
    csr_scatter<<<(E + 255) / 256, 256>>>(ei, ew, E);

    for (int l = 0; l < NLYR; ++l) {
        spmm_csr<<<(int)(((size_t)n * 32 + 255) / 256), 256>>>(n);
        fused_layer_mma<<<(n + 63) / 64, 256, DSM_BYTES>>>(gcb, bib, n, l);
    }

    score<<<(int)(((size_t)Q * 32 + 255) / 256), 256>>>(eli, Q, out);
}

// round 15
// speedup vs baseline: 1.1279x; 1.0221x over previous
#include <cuda_runtime.h>
#include <cuda_fp16.h>
#include <cstdint>

#define NMAX 100000
#define EMAX 1600000
#define NLYR 3

// Device scratch.
__device__ __align__(16) float  g_all[(size_t)NMAX * 512];
__device__ __align__(16) __half g_allH[(size_t)NMAX * 512];  // fp16 concat (score gather)
__device__ __align__(16) float  g_ego[(size_t)NMAX * 128];   // fp32 ego (GEMM product term)
__device__ __align__(16) __half g_egoH[(size_t)NMAX * 128];  // fp16 ego (SpMM gather)
__device__ __align__(16) float  g_msg[(size_t)NMAX * 128];
// Pre-split bf16 weights: [l][chunk 0..7][hi/lo][od 0..127][k 0..31]
__device__ __align__(16) unsigned short g_wbf[NLYR * 8 * 2 * 128 * 32];
// CSR built once per launch.
__device__ int   g_rowptr[NMAX];
__device__ int   g_cnt[NMAX];
__device__ int   g_off[NMAX];
__device__ int   g_total;
__device__ int   g_ecol[EMAX];
__device__ float g_ewc[EMAX];

// ---------------------------------------------------------------------------
__device__ __forceinline__ uint32_t smem_to_u32(const void* p) {
    uint32_t a;
    asm("{ .reg .u64 t; cvta.to.shared.u64 t, %1; cvt.u32.u64 %0, t; }"
        : "=r"(a) : "l"(p));
    return a;
}
__device__ __forceinline__ uint32_t bf16x2_of(float a, float b) {
    uint32_t r;
    asm("cvt.rn.bf16x2.f32 %0, %1, %2;" : "=r"(r) : "f"(a), "f"(b));
    return r;
}
__device__ __forceinline__ void ldmx4(uint32_t* r, uint32_t addr) {
    asm volatile("ldmatrix.sync.aligned.m8n8.x4.shared.b16 {%0,%1,%2,%3}, [%4];"
                 : "=r"(r[0]), "=r"(r[1]), "=r"(r[2]), "=r"(r[3]) : "r"(addr));
}
__device__ __forceinline__ void mma_bf16(float* c, const uint32_t* a,
                                         const uint32_t* b) {
    asm volatile(
        "mma.sync.aligned.m16n8k16.row.col.f32.bf16.bf16.f32 "
        "{%0,%1,%2,%3}, {%4,%5,%6,%7}, {%8,%9}, {%0,%1,%2,%3};"
        : "+f"(c[0]), "+f"(c[1]), "+f"(c[2]), "+f"(c[3])
        : "r"(a[0]), "r"(a[1]), "r"(a[2]), "r"(a[3]), "r"(b[0]), "r"(b[1]));
}
__device__ __forceinline__ void cpasync16(uint32_t daddr, const void* src) {
    asm volatile("cp.async.cg.shared.global [%0], [%1], 16;"
                 :: "r"(daddr), "l"(src) : "memory");
}
#define CP_COMMIT() asm volatile("cp.async.commit_group;" ::: "memory")
#define CP_WAIT1()  asm volatile("cp.async.wait_group 1;" ::: "memory")
#define CP_WAIT0()  asm volatile("cp.async.wait_group 0;" ::: "memory")

// pack float4 -> 2x half2 (uint2)
__device__ __forceinline__ uint2 f4_to_h4(float4 v) {
    __half2 a = __floats2half2_rn(v.x, v.y);
    __half2 b = __floats2half2_rn(v.z, v.w);
    uint2 r;
    r.x = *reinterpret_cast<uint32_t*>(&a);
    r.y = *reinterpret_cast<uint32_t*>(&b);
    return r;
}
__device__ __forceinline__ float4 h4_to_f4(uint2 u) {
    __half2 a = *reinterpret_cast<__half2*>(&u.x);
    __half2 b = *reinterpret_cast<__half2*>(&u.y);
    float2 f0 = __half22float2(a);
    float2 f1 = __half22float2(b);
    return make_float4(f0.x, f0.y, f1.x, f1.y);
}

// ---------------------------------------------------------------------------
// pack_weights: stacked [gc_w | bi_w] K=256, split to bf16 hi+lo.
// ---------------------------------------------------------------------------
__global__ void pack_weights(const float* __restrict__ gw,
                             const float* __restrict__ bw) {
    int idx = blockIdx.x * blockDim.x + threadIdx.x;
    if (idx >= NLYR * 128 * 256) return;
    int l  = idx >> 15;
    int r  = idx & 32767;
    int od = r >> 8;
    int k  = r & 255;
    float x = (k < 128) ? gw[l * 16384 + od * 128 + k]
                        : bw[l * 16384 + od * 128 + (k - 128)];
    uint32_t h2 = bf16x2_of(x, x);
    float xh = __uint_as_float(h2 & 0xffff0000u);
    uint32_t l2 = bf16x2_of(x - xh, x - xh);
    int c = k >> 5, q = k & 31;
    size_t base = ((size_t)((l * 8 + c) * 2) * 128 + od) * 32 + q;
    g_wbf[base]            = (unsigned short)(h2 >> 16);
    g_wbf[base + 128 * 32] = (unsigned short)(l2 >> 16);
}

// ---------------------------------------------------------------------------
__global__ void init_copy(const float4* __restrict__ emb4, int n) {
    int i = blockIdx.x * blockDim.x + threadIdx.x;
    if (i >= n * 32) return;
    int node = i >> 5, d4 = i & 31;
    float4 v = emb4[i];
    ((float4*)g_all)[(size_t)node * 128 + d4] = v;
    ((uint2*)g_allH)[(size_t)node * 128 + d4] = f4_to_h4(v);
    ((float4*)g_ego)[i] = v;
    ((uint2*)g_egoH)[i] = f4_to_h4(v);
    if (d4 == 0) { g_cnt[node] = 0; g_off[node] = 0; }
    if (i == 0) g_total = 0;
}

// ---------------------------------------------------------------------------
// CSR build (proven path).
// ---------------------------------------------------------------------------
__global__ void csr_hist(const int* __restrict__ ei, int E) {
    int e = blockIdx.x * blockDim.x + threadIdx.x;
    if (e < E) atomicAdd(&g_cnt[ei[e]], 1);
}

__global__ __launch_bounds__(256) void csr_offsets(int n) {
    __shared__ int wbase[8];
    int tid  = threadIdx.x;
    int lane = tid & 31;
    int w    = tid >> 5;
    int i    = blockIdx.x * 256 + tid;
    int cnt  = (i < n) ? g_cnt[i] : 0;

    int pre = cnt;
#pragma unroll
    for (int off = 1; off < 32; off <<= 1) {
        int v = __shfl_up_sync(0xffffffffu, pre, off);
        if (lane >= off) pre += v;
    }
    if (lane == 31) wbase[w] = pre;
    __syncthreads();
    if (w == 0) {
        int orig = (lane < 8) ? wbase[lane] : 0;
        int s = orig;
#pragma unroll
        for (int off = 1; off < 8; off <<= 1) {
            int v = __shfl_up_sync(0xffffffffu, s, off);
            if (lane >= off) s += v;
        }
        int total = __shfl_sync(0xffffffffu, s, 7);
        int base = 0;
        if (lane == 7) base = atomicAdd(&g_total, total);
        base = __shfl_sync(0xffffffffu, base, 7);
        if (lane < 8) wbase[lane] = base + s - orig;
    }
    __syncthreads();
    if (i < n) g_rowptr[i] = wbase[w] + pre - cnt;
}

__global__ void csr_scatter(const int* __restrict__ ei,
                            const float* __restrict__ ew, int E) {
    int e = blockIdx.x * blockDim.x + threadIdx.x;
    if (e >= E) return;
    int row = ei[e];
    int col = ei[E + e];
    int pos = g_rowptr[row] + atomicAdd(&g_off[row], 1);
    g_ecol[pos] = col;
    g_ewc[pos]  = ew[e];
}

// ---------------------------------------------------------------------------
// SpMM via CSR, fp16 ego gather (256 B/row). fp32 accumulate.
// ---------------------------------------------------------------------------
__global__ void spmm_csr(int n) {
    int gt = blockIdx.x * blockDim.x + threadIdx.x;
    int row = gt >> 5, lane = gt & 31;
    if (row >= n) return;
    int beg = g_rowptr[row];
    int end = beg + g_cnt[row];
    float4 acc = make_float4(0.f, 0.f, 0.f, 0.f);
    const uint2* egoH2 = (const uint2*)g_egoH;
    for (int b = beg; b < end; b += 32) {
        int idx = b + lane;
        int c = 0; float w = 0.f;
        if (idx < end) { c = g_ecol[idx]; w = g_ewc[idx]; }
        int m = min(32, end - b);
        for (int j = 0; j < m; ++j) {
            int   cc = __shfl_sync(0xffffffffu, c, j);
            float ww = __shfl_sync(0xffffffffu, w, j);
            float4 v = h4_to_f4(egoH2[(size_t)cc * 32 + lane]);
            acc.x += ww * v.x; acc.y += ww * v.y;
            acc.z += ww * v.z; acc.w += ww * v.w;
        }
    }
    ((float4*)g_msg)[(size_t)row * 32 + lane] = acc;
}

// ---------------------------------------------------------------------------
// Fused layer via warp-level split-bf16 HMMA, pipelined fills (proven R13):
//   W: cp.async double-buffered; A: register-prefetch.
//   C[64 nodes][128 od] = A[64][256] * W[128][256]^T, A = [msg | ego*msg]
//   3 terms: Ah*Wh + Ah*Wl + Al*Wh, fp32 register accumulate.
// ---------------------------------------------------------------------------
#define PITCH 40                   // shorts per row (80 B), ldmatrix-safe
#define TA_H  0
#define TA_L  5120
#define TW0   10240
#define TW1   30720
#define DSM_BYTES 51200

__global__ __launch_bounds__(256, 2) void fused_layer_mma(
        const float* __restrict__ gcb, const float* __restrict__ bib,
        int n, int layer) {
    extern __shared__ __align__(16) char dsm[];
    __shared__ float biasS[128];
    __shared__ float part[64];
    __shared__ float invS[64];

    const int tid  = threadIdx.x;
    const int lane = tid & 31;
    const int w    = tid >> 5;
    const int wm   = w >> 2;
    const int wn   = w & 3;
    const int m0   = wm * 32;
    const int n0   = wn * 32;
    const int nb   = blockIdx.x * 64;
    const int loff = layer * 128;
    const uint32_t sb = smem_to_u32(dsm);

    if (tid < 128) biasS[tid] = gcb[loff + tid] + bib[loff + tid];
    if (tid < 64)  part[tid] = 0.f;

    float acc[2][4][4];
#pragma unroll
    for (int a = 0; a < 2; ++a)
#pragma unroll
        for (int b = 0; b < 4; ++b)
#pragma unroll
            for (int c = 0; c < 4; ++c) acc[a][b][c] = 0.f;

    const unsigned short* wsrc = g_wbf + (size_t)layer * 8 * 2 * 128 * 32;

    const int an0 = tid >> 3;
    const int aq  = tid & 7;
    const int an1 = (tid + 256) >> 3;
    const bool ok0 = (nb + an0) < n;
    const bool ok1 = (nb + an1) < n;
    const float4* msg4 = (const float4*)g_msg;
    const float4* ego4 = (const float4*)g_ego;
    const float4 z4 = make_float4(0.f, 0.f, 0.f, 0.f);

    // ---- prologue: cp.async W chunk 0 -> buf0; load A chunk 0 regs ----
    {
        const uint4* src = (const uint4*)wsrc;
#pragma unroll
        for (int i = 0; i < 4; ++i) {
            int idx = tid + 256 * i;
            int h   = idx >> 9;
            int rem = idx & 511;
            int row = rem >> 2;
            int seg = rem & 3;
            cpasync16(sb + TW0 + h * 10240 + row * (PITCH * 2) + seg * 16,
                      src + idx);
        }
        CP_COMMIT();
    }
    float4 pm0, pm1, pe0, pe1;
    pm0 = ok0 ? msg4[(size_t)(nb + an0) * 32 + aq] : z4;
    pm1 = ok1 ? msg4[(size_t)(nb + an1) * 32 + aq] : z4;
    pe0 = z4; pe1 = z4;

    for (int c = 0; c < 8; ++c) {
        // ---- STS A chunk c from prefetch regs (split hi/lo) ----
        {
            float4 xs[2];
            if (c < 4) { xs[0] = pm0; xs[1] = pm1; }
            else {
                xs[0] = make_float4(pm0.x * pe0.x, pm0.y * pe0.y,
                                    pm0.z * pe0.z, pm0.w * pe0.w);
                xs[1] = make_float4(pm1.x * pe1.x, pm1.y * pe1.y,
                                    pm1.z * pe1.z, pm1.w * pe1.w);
            }
#pragma unroll
            for (int i = 0; i < 2; ++i) {
                float4 x = xs[i];
                int node = i ? an1 : an0;
                uint32_t h01 = bf16x2_of(x.y, x.x);
                uint32_t h23 = bf16x2_of(x.w, x.z);
                float a0 = __uint_as_float(h01 << 16);
                float a1 = __uint_as_float(h01 & 0xffff0000u);
                float a2 = __uint_as_float(h23 << 16);
                float a3 = __uint_as_float(h23 & 0xffff0000u);
                uint32_t l01 = bf16x2_of(x.y - a1, x.x - a0);
                uint32_t l23 = bf16x2_of(x.w - a3, x.z - a2);
                *(uint2*)(dsm + TA_H + node * (PITCH * 2) + aq * 8) =
                    make_uint2(h01, h23);
                *(uint2*)(dsm + TA_L + node * (PITCH * 2) + aq * 8) =
                    make_uint2(l01, l23);
            }
        }

        // ---- issue next chunk's W cp.async + A LDGs ----
        if (c < 7) {
            int nc = c + 1;
            const uint4* src = (const uint4*)(wsrc + (size_t)(nc * 2) * 128 * 32);
            uint32_t base = sb + ((nc & 1) ? TW1 : TW0);
#pragma unroll
            for (int i = 0; i < 4; ++i) {
                int idx = tid + 256 * i;
                int h   = idx >> 9;
                int rem = idx & 511;
                int row = rem >> 2;
                int seg = rem & 3;
                cpasync16(base + h * 10240 + row * (PITCH * 2) + seg * 16,
                          src + idx);
            }
            CP_COMMIT();
            if (nc < 4) {
                pm0 = ok0 ? msg4[(size_t)(nb + an0) * 32 + nc * 8 + aq] : z4;
                pm1 = ok1 ? msg4[(size_t)(nb + an1) * 32 + nc * 8 + aq] : z4;
            } else {
                int kk = (nc - 4) * 8 + aq;
                pm0 = ok0 ? msg4[(size_t)(nb + an0) * 32 + kk] : z4;
                pm1 = ok1 ? msg4[(size_t)(nb + an1) * 32 + kk] : z4;
                pe0 = ok0 ? ego4[(size_t)(nb + an0) * 32 + kk] : z4;
                pe1 = ok1 ? ego4[(size_t)(nb + an1) * 32 + kk] : z4;
            }
            CP_WAIT1();
        } else {
            CP_WAIT0();
        }
        __syncthreads();

        // ---- compute chunk c: 2 k16 steps ----
        const uint32_t wb = sb + ((c & 1) ? TW1 : TW0);
#pragma unroll
        for (int kb = 0; kb < 2; ++kb) {
            uint32_t Ah[2][4], Al[2][4], Wh[2][4], Wl[2][4];
            {
                int arow = lane & 15;
                uint32_t aoff = (uint32_t)((lane >> 4) * 16 + kb * 32);
#pragma unroll
                for (int mt = 0; mt < 2; ++mt) {
                    uint32_t ra = sb + TA_H +
                        (uint32_t)(m0 + mt * 16 + arow) * (PITCH * 2) + aoff;
                    ldmx4(Ah[mt], ra);
                    ldmx4(Al[mt], ra + (TA_L - TA_H));
                }
            }
            {
                int g2 = lane >> 3, r2 = lane & 7;
                int wrow = n0 + r2 + ((g2 >> 1) << 3);
                uint32_t woff = (uint32_t)((g2 & 1) * 16 + kb * 32);
#pragma unroll
                for (int nt2 = 0; nt2 < 2; ++nt2) {
                    uint32_t rw = wb +
                        (uint32_t)(wrow + nt2 * 16) * (PITCH * 2) + woff;
                    ldmx4(Wh[nt2], rw);
                    ldmx4(Wl[nt2], rw + 10240);
                }
            }
#pragma unroll
            for (int mt = 0; mt < 2; ++mt) {
#pragma unroll
                for (int nt = 0; nt < 4; ++nt) {
                    const uint32_t* bh = &Wh[nt >> 1][(nt & 1) * 2];
                    const uint32_t* bl = &Wl[nt >> 1][(nt & 1) * 2];
                    mma_bf16(acc[mt][nt], Ah[mt], bh);
                    mma_bf16(acc[mt][nt], Ah[mt], bl);
                    mma_bf16(acc[mt][nt], Al[mt], bh);
                }
            }
        }
        __syncthreads();
    }

    // ==== epilogue ====
    float* Vs = (float*)dsm;          // [64][132] overlays tiles
    float rs[2][2] = {{0.f, 0.f}, {0.f, 0.f}};
#pragma unroll
    for (int mt = 0; mt < 2; ++mt) {
#pragma unroll
        for (int nt = 0; nt < 4; ++nt) {
            int row0 = m0 + mt * 16 + (lane >> 2);
            int col  = n0 + nt * 8 + (lane & 3) * 2;
            float b0 = biasS[col], b1 = biasS[col + 1];
            float x0 = acc[mt][nt][0] + b0;
            float x1 = acc[mt][nt][1] + b1;
            float x2 = acc[mt][nt][2] + b0;
            float x3 = acc[mt][nt][3] + b1;
            x0 = (x0 > 0.f) ? x0 : 0.2f * x0;
            x1 = (x1 > 0.f) ? x1 : 0.2f * x1;
            x2 = (x2 > 0.f) ? x2 : 0.2f * x2;
            x3 = (x3 > 0.f) ? x3 : 0.2f * x3;
            Vs[row0 * 132 + col]           = x0;
            Vs[row0 * 132 + col + 1]       = x1;
            Vs[(row0 + 8) * 132 + col]     = x2;
            Vs[(row0 + 8) * 132 + col + 1] = x3;
            rs[mt][0] += x0 * x0 + x1 * x1;
            rs[mt][1] += x2 * x2 + x3 * x3;
        }
    }
#pragma unroll
    for (int mt = 0; mt < 2; ++mt)
#pragma unroll
        for (int hh = 0; hh < 2; ++hh) {
            float v = rs[mt][hh];
            v += __shfl_xor_sync(0xffffffffu, v, 1);
            v += __shfl_xor_sync(0xffffffffu, v, 2);
            if ((lane & 3) == 0)
                atomicAdd(&part[m0 + mt * 16 + hh * 8 + (lane >> 2)], v);
        }
    __syncthreads();
    if (tid < 64) invS[tid] = 1.0f / fmaxf(sqrtf(part[tid]), 1e-12f);
    __syncthreads();

    for (int i = tid; i < 64 * 32; i += 256) {
        int node = i >> 5, d4 = i & 31;
        int g = nb + node;
        if (g < n) {
            const float* p = Vs + node * 132 + d4 * 4;
            float inv = invS[node];
            float4 v = make_float4(p[0], p[1], p[2], p[3]);
            *(float4*)(g_ego + (size_t)g * 128 + d4 * 4) = v;
            ((uint2*)g_egoH)[(size_t)g * 32 + d4] = f4_to_h4(v);
            float4 nv = make_float4(v.x * inv, v.y * inv, v.z * inv, v.w * inv);
            *(float4*)(g_all + (size_t)g * 512 + loff + 128 + d4 * 4) = nv;
            ((uint2*)g_allH)[(size_t)g * 128 + (loff + 128) / 4 + d4] = f4_to_h4(nv);
        }
    }
}

// ---------------------------------------------------------------------------
// Scoring: fp16 gather (half the bytes), fp32 accumulate. Warp per query.
// ---------------------------------------------------------------------------
__global__ void score(const int* __restrict__ eli, int Q,
                      float* __restrict__ out) {
    int gt = blockIdx.x * blockDim.x + threadIdx.x;
    int q = gt >> 5, lane = gt & 31;
    if (q >= Q) return;
    int s = eli[q];
    int d = eli[Q + q];
    const uint2* a = (const uint2*)(g_allH + (size_t)s * 512);
    const uint2* b = (const uint2*)(g_allH + (size_t)d * 512);
    float acc = 0.f;
#pragma unroll
    for (int j = 0; j < 4; ++j) {
        float4 x = h4_to_f4(a[lane + 32 * j]);
        float4 y = h4_to_f4(b[lane + 32 * j]);
        acc += x.x * y.x + x.y * y.y + x.z * y.z + x.w * y.w;
    }
#pragma unroll
    for (int off = 16; off; off >>= 1)
        acc += __shfl_xor_sync(0xffffffffu, acc, off);
    if (lane == 0) out[q] = acc;
}

// ---------------------------------------------------------------------------
extern "C" void kernel_launch(void* const* d_in, const int* in_sizes, int n_in,
                              void* d_out, int out_size) {
    const int*   ei  = (const int*)d_in[0];
    const int*   eli = (const int*)d_in[1];
    const float* ew  = (const float*)d_in[2];
    const float* emb = (const float*)d_in[3];
    const float* gcw = (const float*)d_in[4];
    const float* gcb = (const float*)d_in[5];
    const float* biw = (const float*)d_in[6];
    const float* bib = (const float*)d_in[7];

    int E = in_sizes[0] / 2;
    int Q = in_sizes[1] / 2;
    int n = in_sizes[3] / 128;
    float* out = (float*)d_out;

    // Idempotent attribute set (not a stream op; capture-safe).
    cudaFuncSetAttribute(fused_layer_mma,
                         cudaFuncAttributeMaxDynamicSharedMemorySize,
                         DSM_BYTES);

    pack_weights<<<(NLYR * 128 * 256 + 255) / 256, 256>>>(gcw, biw);
    init_copy<<<(n * 32 + 255) / 256, 256>>>((const float4*)emb, n);

    csr_hist<<<(E + 255) / 256, 256>>>(ei, E);
    csr_offsets<<<(n + 255) / 256, 256>>>(n);
    csr_scatter<<<(E + 255) / 256, 256>>>(ei, ew, E);

    for (int l = 0; l < NLYR; ++l) {
        spmm_csr<<<(int)(((size_t)n * 32 + 255) / 256), 256>>>(n);
        fused_layer_mma<<<(n + 63) / 64, 256, DSM_BYTES>>>(gcb, bib, n, l);
    }

    score<<<(int)(((size_t)Q * 32 + 255) / 256), 256>>>(eli, Q, out);
}

// round 16
// speedup vs baseline: 1.1549x; 1.0239x over previous
#include <cuda_runtime.h>
#include <cuda_fp16.h>
#include <cstdint>

#define NMAX 100000
#define EMAX 1600000
#define NLYR 3

// Device scratch.
__device__ __align__(16) float  g_all[(size_t)NMAX * 512];
__device__ __align__(16) __half g_allH[(size_t)NMAX * 512];  // fp16 concat (score gather)
__device__ __align__(16) float  g_ego[(size_t)NMAX * 128];   // fp32 ego (GEMM product term)
__device__ __align__(16) __half g_egoH[(size_t)NMAX * 128];  // fp16 ego (SpMM gather)
__device__ __align__(16) float  g_msg[(size_t)NMAX * 128];
// Pre-split bf16 weights: [l][chunk 0..7][hi/lo][od 0..127][k 0..31]
__device__ __align__(16) unsigned short g_wbf[NLYR * 8 * 2 * 128 * 32];
// CSR built once per launch.
__device__ int   g_rowptr[NMAX];
__device__ int   g_cnt[NMAX];
__device__ int   g_off[NMAX];
__device__ int   g_total;
__device__ int   g_ecol[EMAX];
__device__ float g_ewc[EMAX];

// ---------------------------------------------------------------------------
__device__ __forceinline__ uint32_t smem_to_u32(const void* p) {
    uint32_t a;
    asm("{ .reg .u64 t; cvta.to.shared.u64 t, %1; cvt.u32.u64 %0, t; }"
        : "=r"(a) : "l"(p));
    return a;
}
__device__ __forceinline__ uint32_t bf16x2_of(float a, float b) {
    uint32_t r;
    asm("cvt.rn.bf16x2.f32 %0, %1, %2;" : "=r"(r) : "f"(a), "f"(b));
    return r;
}
__device__ __forceinline__ void ldmx4(uint32_t* r, uint32_t addr) {
    asm volatile("ldmatrix.sync.aligned.m8n8.x4.shared.b16 {%0,%1,%2,%3}, [%4];"
                 : "=r"(r[0]), "=r"(r[1]), "=r"(r[2]), "=r"(r[3]) : "r"(addr));
}
__device__ __forceinline__ void mma_bf16(float* c, const uint32_t* a,
                                         const uint32_t* b) {
    asm volatile(
        "mma.sync.aligned.m16n8k16.row.col.f32.bf16.bf16.f32 "
        "{%0,%1,%2,%3}, {%4,%5,%6,%7}, {%8,%9}, {%0,%1,%2,%3};"
        : "+f"(c[0]), "+f"(c[1]), "+f"(c[2]), "+f"(c[3])
        : "r"(a[0]), "r"(a[1]), "r"(a[2]), "r"(a[3]), "r"(b[0]), "r"(b[1]));
}
__device__ __forceinline__ void cpasync16(uint32_t daddr, const void* src) {
    asm volatile("cp.async.cg.shared.global [%0], [%1], 16;"
                 :: "r"(daddr), "l"(src) : "memory");
}
#define CP_COMMIT() asm volatile("cp.async.commit_group;" ::: "memory")
#define CP_WAIT1()  asm volatile("cp.async.wait_group 1;" ::: "memory")
#define CP_WAIT0()  asm volatile("cp.async.wait_group 0;" ::: "memory")

// pack float4 -> 2x half2 (uint2)
__device__ __forceinline__ uint2 f4_to_h4(float4 v) {
    __half2 a = __floats2half2_rn(v.x, v.y);
    __half2 b = __floats2half2_rn(v.z, v.w);
    uint2 r;
    r.x = *reinterpret_cast<uint32_t*>(&a);
    r.y = *reinterpret_cast<uint32_t*>(&b);
    return r;
}
__device__ __forceinline__ float4 h4_to_f4(uint2 u) {
    __half2 a = *reinterpret_cast<__half2*>(&u.x);
    __half2 b = *reinterpret_cast<__half2*>(&u.y);
    float2 f0 = __half22float2(a);
    float2 f1 = __half22float2(b);
    return make_float4(f0.x, f0.y, f1.x, f1.y);
}

// ---------------------------------------------------------------------------
// pack_weights: stacked [gc_w | bi_w] K=256, split to bf16 hi+lo.
// ---------------------------------------------------------------------------
__global__ void pack_weights(const float* __restrict__ gw,
                             const float* __restrict__ bw) {
    int idx = blockIdx.x * blockDim.x + threadIdx.x;
    if (idx >= NLYR * 128 * 256) return;
    int l  = idx >> 15;
    int r  = idx & 32767;
    int od = r >> 8;
    int k  = r & 255;
    float x = (k < 128) ? gw[l * 16384 + od * 128 + k]
                        : bw[l * 16384 + od * 128 + (k - 128)];
    uint32_t h2 = bf16x2_of(x, x);
    float xh = __uint_as_float(h2 & 0xffff0000u);
    uint32_t l2 = bf16x2_of(x - xh, x - xh);
    int c = k >> 5, q = k & 31;
    size_t base = ((size_t)((l * 8 + c) * 2) * 128 + od) * 32 + q;
    g_wbf[base]            = (unsigned short)(h2 >> 16);
    g_wbf[base + 128 * 32] = (unsigned short)(l2 >> 16);
}

// ---------------------------------------------------------------------------
__global__ void init_copy(const float4* __restrict__ emb4, int n) {
    int i = blockIdx.x * blockDim.x + threadIdx.x;
    if (i >= n * 32) return;
    int node = i >> 5, d4 = i & 31;
    float4 v = emb4[i];
    ((float4*)g_all)[(size_t)node * 128 + d4] = v;
    ((uint2*)g_allH)[(size_t)node * 128 + d4] = f4_to_h4(v);
    ((float4*)g_ego)[i] = v;
    ((uint2*)g_egoH)[i] = f4_to_h4(v);
    if (d4 == 0) { g_cnt[node] = 0; g_off[node] = 0; }
    if (i == 0) g_total = 0;
}

// ---------------------------------------------------------------------------
// CSR build (proven path).
// ---------------------------------------------------------------------------
__global__ void csr_hist(const int* __restrict__ ei, int E) {
    int e = blockIdx.x * blockDim.x + threadIdx.x;
    if (e < E) atomicAdd(&g_cnt[ei[e]], 1);
}

__global__ __launch_bounds__(256) void csr_offsets(int n) {
    __shared__ int wbase[8];
    int tid  = threadIdx.x;
    int lane = tid & 31;
    int w    = tid >> 5;
    int i    = blockIdx.x * 256 + tid;
    int cnt  = (i < n) ? g_cnt[i] : 0;

    int pre = cnt;
#pragma unroll
    for (int off = 1; off < 32; off <<= 1) {
        int v = __shfl_up_sync(0xffffffffu, pre, off);
        if (lane >= off) pre += v;
    }
    if (lane == 31) wbase[w] = pre;
    __syncthreads();
    if (w == 0) {
        int orig = (lane < 8) ? wbase[lane] : 0;
        int s = orig;
#pragma unroll
        for (int off = 1; off < 8; off <<= 1) {
            int v = __shfl_up_sync(0xffffffffu, s, off);
            if (lane >= off) s += v;
        }
        int total = __shfl_sync(0xffffffffu, s, 7);
        int base = 0;
        if (lane == 7) base = atomicAdd(&g_total, total);
        base = __shfl_sync(0xffffffffu, base, 7);
        if (lane < 8) wbase[lane] = base + s - orig;
    }
    __syncthreads();
    if (i < n) g_rowptr[i] = wbase[w] + pre - cnt;
}

__global__ void csr_scatter(const int* __restrict__ ei,
                            const float* __restrict__ ew, int E) {
    int e = blockIdx.x * blockDim.x + threadIdx.x;
    if (e >= E) return;
    int row = ei[e];
    int col = ei[E + e];
    int pos = g_rowptr[row] + atomicAdd(&g_off[row], 1);
    g_ecol[pos] = col;
    g_ewc[pos]  = ew[e];
}

// ---------------------------------------------------------------------------
// SpMM via CSR, fp16 ego gather, MLP-4 unrolled inner loop:
// 4 independent row-gathers in flight per step (latency /4).
// ---------------------------------------------------------------------------
__global__ void spmm_csr(int n) {
    int gt = blockIdx.x * blockDim.x + threadIdx.x;
    int row = gt >> 5, lane = gt & 31;
    if (row >= n) return;
    int beg = g_rowptr[row];
    int end = beg + g_cnt[row];
    float4 acc = make_float4(0.f, 0.f, 0.f, 0.f);
    const uint2* egoH2 = (const uint2*)g_egoH;
    for (int b = beg; b < end; b += 32) {
        int idx = b + lane;
        int c = 0; float w = 0.f;
        if (idx < end) { c = g_ecol[idx]; w = g_ewc[idx]; }
        int m = min(32, end - b);
        int j = 0;
        for (; j + 4 <= m; j += 4) {
            int   c0 = __shfl_sync(0xffffffffu, c, j);
            int   c1 = __shfl_sync(0xffffffffu, c, j + 1);
            int   c2 = __shfl_sync(0xffffffffu, c, j + 2);
            int   c3 = __shfl_sync(0xffffffffu, c, j + 3);
            float w0 = __shfl_sync(0xffffffffu, w, j);
            float w1 = __shfl_sync(0xffffffffu, w, j + 1);
            float w2 = __shfl_sync(0xffffffffu, w, j + 2);
            float w3 = __shfl_sync(0xffffffffu, w, j + 3);
            uint2 u0 = egoH2[(size_t)c0 * 32 + lane];
            uint2 u1 = egoH2[(size_t)c1 * 32 + lane];
            uint2 u2 = egoH2[(size_t)c2 * 32 + lane];
            uint2 u3 = egoH2[(size_t)c3 * 32 + lane];
            float4 v0 = h4_to_f4(u0);
            float4 v1 = h4_to_f4(u1);
            float4 v2 = h4_to_f4(u2);
            float4 v3 = h4_to_f4(u3);
            acc.x += w0 * v0.x; acc.y += w0 * v0.y;
            acc.z += w0 * v0.z; acc.w += w0 * v0.w;
            acc.x += w1 * v1.x; acc.y += w1 * v1.y;
            acc.z += w1 * v1.z; acc.w += w1 * v1.w;
            acc.x += w2 * v2.x; acc.y += w2 * v2.y;
            acc.z += w2 * v2.z; acc.w += w2 * v2.w;
            acc.x += w3 * v3.x; acc.y += w3 * v3.y;
            acc.z += w3 * v3.z; acc.w += w3 * v3.w;
        }
        for (; j < m; ++j) {
            int   cc = __shfl_sync(0xffffffffu, c, j);
            float ww = __shfl_sync(0xffffffffu, w, j);
            float4 v = h4_to_f4(egoH2[(size_t)cc * 32 + lane]);
            acc.x += ww * v.x; acc.y += ww * v.y;
            acc.z += ww * v.z; acc.w += ww * v.w;
        }
    }
    ((float4*)g_msg)[(size_t)row * 32 + lane] = acc;
}

// ---------------------------------------------------------------------------
// Fused layer via warp-level split-bf16 HMMA, pipelined fills (proven R13):
//   W: cp.async double-buffered; A: register-prefetch.
//   C[64 nodes][128 od] = A[64][256] * W[128][256]^T, A = [msg | ego*msg]
//   3 terms: Ah*Wh + Ah*Wl + Al*Wh, fp32 register accumulate.
// ---------------------------------------------------------------------------
#define PITCH 40                   // shorts per row (80 B), ldmatrix-safe
#define TA_H  0
#define TA_L  5120
#define TW0   10240
#define TW1   30720
#define DSM_BYTES 51200

__global__ __launch_bounds__(256, 2) void fused_layer_mma(
        const float* __restrict__ gcb, const float* __restrict__ bib,
        int n, int layer) {
    extern __shared__ __align__(16) char dsm[];
    __shared__ float biasS[128];
    __shared__ float part[64];
    __shared__ float invS[64];

    const int tid  = threadIdx.x;
    const int lane = tid & 31;
    const int w    = tid >> 5;
    const int wm   = w >> 2;
    const int wn   = w & 3;
    const int m0   = wm * 32;
    const int n0   = wn * 32;
    const int nb   = blockIdx.x * 64;
    const int loff = layer * 128;
    const uint32_t sb = smem_to_u32(dsm);

    if (tid < 128) biasS[tid] = gcb[loff + tid] + bib[loff + tid];
    if (tid < 64)  part[tid] = 0.f;

    float acc[2][4][4];
#pragma unroll
    for (int a = 0; a < 2; ++a)
#pragma unroll
        for (int b = 0; b < 4; ++b)
#pragma unroll
            for (int c = 0; c < 4; ++c) acc[a][b][c] = 0.f;

    const unsigned short* wsrc = g_wbf + (size_t)layer * 8 * 2 * 128 * 32;

    const int an0 = tid >> 3;
    const int aq  = tid & 7;
    const int an1 = (tid + 256) >> 3;
    const bool ok0 = (nb + an0) < n;
    const bool ok1 = (nb + an1) < n;
    const float4* msg4 = (const float4*)g_msg;
    const float4* ego4 = (const float4*)g_ego;
    const float4 z4 = make_float4(0.f, 0.f, 0.f, 0.f);

    // ---- prologue: cp.async W chunk 0 -> buf0; load A chunk 0 regs ----
    {
        const uint4* src = (const uint4*)wsrc;
#pragma unroll
        for (int i = 0; i < 4; ++i) {
            int idx = tid + 256 * i;
            int h   = idx >> 9;
            int rem = idx & 511;
            int row = rem >> 2;
            int seg = rem & 3;
            cpasync16(sb + TW0 + h * 10240 + row * (PITCH * 2) + seg * 16,
                      src + idx);
        }
        CP_COMMIT();
    }
    float4 pm0, pm1, pe0, pe1;
    pm0 = ok0 ? msg4[(size_t)(nb + an0) * 32 + aq] : z4;
    pm1 = ok1 ? msg4[(size_t)(nb + an1) * 32 + aq] : z4;
    pe0 = z4; pe1 = z4;

    for (int c = 0; c < 8; ++c) {
        // ---- STS A chunk c from prefetch regs (split hi/lo) ----
        {
            float4 xs[2];
            if (c < 4) { xs[0] = pm0; xs[1] = pm1; }
            else {
                xs[0] = make_float4(pm0.x * pe0.x, pm0.y * pe0.y,
                                    pm0.z * pe0.z, pm0.w * pe0.w);
                xs[1] = make_float4(pm1.x * pe1.x, pm1.y * pe1.y,
                                    pm1.z * pe1.z, pm1.w * pe1.w);
            }
#pragma unroll
            for (int i = 0; i < 2; ++i) {
                float4 x = xs[i];
                int node = i ? an1 : an0;
                uint32_t h01 = bf16x2_of(x.y, x.x);
                uint32_t h23 = bf16x2_of(x.w, x.z);
                float a0 = __uint_as_float(h01 << 16);
                float a1 = __uint_as_float(h01 & 0xffff0000u);
                float a2 = __uint_as_float(h23 << 16);
                float a3 = __uint_as_float(h23 & 0xffff0000u);
                uint32_t l01 = bf16x2_of(x.y - a1, x.x - a0);
                uint32_t l23 = bf16x2_of(x.w - a3, x.z - a2);
                *(uint2*)(dsm + TA_H + node * (PITCH * 2) + aq * 8) =
                    make_uint2(h01, h23);
                *(uint2*)(dsm + TA_L + node * (PITCH * 2) + aq * 8) =
                    make_uint2(l01, l23);
            }
        }

        // ---- issue next chunk's W cp.async + A LDGs ----
        if (c < 7) {
            int nc = c + 1;
            const uint4* src = (const uint4*)(wsrc + (size_t)(nc * 2) * 128 * 32);
            uint32_t base = sb + ((nc & 1) ? TW1 : TW0);
#pragma unroll
            for (int i = 0; i < 4; ++i) {
                int idx = tid + 256 * i;
                int h   = idx >> 9;
                int rem = idx & 511;
                int row = rem >> 2;
                int seg = rem & 3;
                cpasync16(base + h * 10240 + row * (PITCH * 2) + seg * 16,
                          src + idx);
            }
            CP_COMMIT();
            if (nc < 4) {
                pm0 = ok0 ? msg4[(size_t)(nb + an0) * 32 + nc * 8 + aq] : z4;
                pm1 = ok1 ? msg4[(size_t)(nb + an1) * 32 + nc * 8 + aq] : z4;
            } else {
                int kk = (nc - 4) * 8 + aq;
                pm0 = ok0 ? msg4[(size_t)(nb + an0) * 32 + kk] : z4;
                pm1 = ok1 ? msg4[(size_t)(nb + an1) * 32 + kk] : z4;
                pe0 = ok0 ? ego4[(size_t)(nb + an0) * 32 + kk] : z4;
                pe1 = ok1 ? ego4[(size_t)(nb + an1) * 32 + kk] : z4;
            }
            CP_WAIT1();
        } else {
            CP_WAIT0();
        }
        __syncthreads();

        // ---- compute chunk c: 2 k16 steps ----
        const uint32_t wb = sb + ((c & 1) ? TW1 : TW0);
#pragma unroll
        for (int kb = 0; kb < 2; ++kb) {
            uint32_t Ah[2][4], Al[2][4], Wh[2][4], Wl[2][4];
            {
                int arow = lane & 15;
                uint32_t aoff = (uint32_t)((lane >> 4) * 16 + kb * 32);
#pragma unroll
                for (int mt = 0; mt < 2; ++mt) {
                    uint32_t ra = sb + TA_H +
                        (uint32_t)(m0 + mt * 16 + arow) * (PITCH * 2) + aoff;
                    ldmx4(Ah[mt], ra);
                    ldmx4(Al[mt], ra + (TA_L - TA_H));
                }
            }
            {
                int g2 = lane >> 3, r2 = lane & 7;
                int wrow = n0 + r2 + ((g2 >> 1) << 3);
                uint32_t woff = (uint32_t)((g2 & 1) * 16 + kb * 32);
#pragma unroll
                for (int nt2 = 0; nt2 < 2; ++nt2) {
                    uint32_t rw = wb +
                        (uint32_t)(wrow + nt2 * 16) * (PITCH * 2) + woff;
                    ldmx4(Wh[nt2], rw);
                    ldmx4(Wl[nt2], rw + 10240);
                }
            }
#pragma unroll
            for (int mt = 0; mt < 2; ++mt) {
#pragma unroll
                for (int nt = 0; nt < 4; ++nt) {
                    const uint32_t* bh = &Wh[nt >> 1][(nt & 1) * 2];
                    const uint32_t* bl = &Wl[nt >> 1][(nt & 1) * 2];
                    mma_bf16(acc[mt][nt], Ah[mt], bh);
                    mma_bf16(acc[mt][nt], Ah[mt], bl);
                    mma_bf16(acc[mt][nt], Al[mt], bh);
                }
            }
        }
        __syncthreads();
    }

    // ==== epilogue ====
    float* Vs = (float*)dsm;          // [64][132] overlays tiles
    float rs[2][2] = {{0.f, 0.f}, {0.f, 0.f}};
#pragma unroll
    for (int mt = 0; mt < 2; ++mt) {
#pragma unroll
        for (int nt = 0; nt < 4; ++nt) {
            int row0 = m0 + mt * 16 + (lane >> 2);
            int col  = n0 + nt * 8 + (lane & 3) * 2;
            float b0 = biasS[col], b1 = biasS[col + 1];
            float x0 = acc[mt][nt][0] + b0;
            float x1 = acc[mt][nt][1] + b1;
            float x2 = acc[mt][nt][2] + b0;
            float x3 = acc[mt][nt][3] + b1;
            x0 = (x0 > 0.f) ? x0 : 0.2f * x0;
            x1 = (x1 > 0.f) ? x1 : 0.2f * x1;
            x2 = (x2 > 0.f) ? x2 : 0.2f * x2;
            x3 = (x3 > 0.f) ? x3 : 0.2f * x3;
            Vs[row0 * 132 + col]           = x0;
            Vs[row0 * 132 + col + 1]       = x1;
            Vs[(row0 + 8) * 132 + col]     = x2;
            Vs[(row0 + 8) * 132 + col + 1] = x3;
            rs[mt][0] += x0 * x0 + x1 * x1;
            rs[mt][1] += x2 * x2 + x3 * x3;
        }
    }
#pragma unroll
    for (int mt = 0; mt < 2; ++mt)
#pragma unroll
        for (int hh = 0; hh < 2; ++hh) {
            float v = rs[mt][hh];
            v += __shfl_xor_sync(0xffffffffu, v, 1);
            v += __shfl_xor_sync(0xffffffffu, v, 2);
            if ((lane & 3) == 0)
                atomicAdd(&part[m0 + mt * 16 + hh * 8 + (lane >> 2)], v);
        }
    __syncthreads();
    if (tid < 64) invS[tid] = 1.0f / fmaxf(sqrtf(part[tid]), 1e-12f);
    __syncthreads();

    for (int i = tid; i < 64 * 32; i += 256) {
        int node = i >> 5, d4 = i & 31;
        int g = nb + node;
        if (g < n) {
            const float* p = Vs + node * 132 + d4 * 4;
            float inv = invS[node];
            float4 v = make_float4(p[0], p[1], p[2], p[3]);
            *(float4*)(g_ego + (size_t)g * 128 + d4 * 4) = v;
            ((uint2*)g_egoH)[(size_t)g * 32 + d4] = f4_to_h4(v);
            float4 nv = make_float4(v.x * inv, v.y * inv, v.z * inv, v.w * inv);
            *(float4*)(g_all + (size_t)g * 512 + loff + 128 + d4 * 4) = nv;
            ((uint2*)g_allH)[(size_t)g * 128 + (loff + 128) / 4 + d4] = f4_to_h4(nv);
        }
    }
}

// ---------------------------------------------------------------------------
// Scoring: fp16 gather (half the bytes), fp32 accumulate. Warp per query.
// ---------------------------------------------------------------------------
__global__ void score(const int* __restrict__ eli, int Q,
                      float* __restrict__ out) {
    int gt = blockIdx.x * blockDim.x + threadIdx.x;
    int q = gt >> 5, lane = gt & 31;
    if (q >= Q) return;
    int s = eli[q];
    int d = eli[Q + q];
    const uint2* a = (const uint2*)(g_allH + (size_t)s * 512);
    const uint2* b = (const uint2*)(g_allH + (size_t)d * 512);
    float acc = 0.f;
#pragma unroll
    for (int j = 0; j < 4; ++j) {
        float4 x = h4_to_f4(a[lane + 32 * j]);
        float4 y = h4_to_f4(b[lane + 32 * j]);
        acc += x.x * y.x + x.y * y.y + x.z * y.z + x.w * y.w;
    }
#pragma unroll
    for (int off = 16; off; off >>= 1)
        acc += __shfl_xor_sync(0xffffffffu, acc, off);
    if (lane == 0) out[q] = acc;
}

// ---------------------------------------------------------------------------
extern "C" void kernel_launch(void* const* d_in, const int* in_sizes, int n_in,
                              void* d_out, int out_size) {
    const int*   ei  = (const int*)d_in[0];
    const int*   eli = (const int*)d_in[1];
    const float* ew  = (const float*)d_in[2];
    const float* emb = (const float*)d_in[3];
    const float* gcw = (const float*)d_in[4];
    const float* gcb = (const float*)d_in[5];
    const float* biw = (const float*)d_in[6];
    const float* bib = (const float*)d_in[7];

    int E = in_sizes[0] / 2;
    int Q = in_sizes[1] / 2;
    int n = in_sizes[3] / 128;
    float* out = (float*)d_out;

    // Idempotent attribute set (not a stream op; capture-safe).
    cudaFuncSetAttribute(fused_layer_mma,
                         cudaFuncAttributeMaxDynamicSharedMemorySize,
                         DSM_BYTES);

    pack_weights<<<(NLYR * 128 * 256 + 255) / 256, 256>>>(gcw, biw);
    init_copy<<<(n * 32 + 255) / 256, 256>>>((const float4*)emb, n);

    csr_hist<<<(E + 255) / 256, 256>>>(ei, E);
    csr_offsets<<<(n + 255) / 256, 256>>>(n);
    csr_scatter<<<(E + 255) / 256, 256>>>(ei, ew, E);

    for (int l = 0; l < NLYR; ++l) {
        spmm_csr<<<(int)(((size_t)n * 32 + 255) / 256), 256>>>(n);
        fused_layer_mma<<<(n + 63) / 64, 256, DSM_BYTES>>>(gcb, bib, n, l);
    }

    score<<<(int)(((size_t)Q * 32 + 255) / 256), 256>>>(eli, Q, out);
}